// round 14
// baseline (speedup 1.0000x reference)
#include <cuda_runtime.h>
#include <cuda_bf16.h>
#include <cuda_fp16.h>
#include <math.h>
#include <cstdint>

#define Bb      2
#define Ll      2048
#define HIDDEN_ 2048
#define PROJ_   8512
#define INTER_  4096
#define CONVD_  4352
#define NH_     64
#define HD_     64
#define ST_     128
#define NC_     8
#define CS_     256
#define MT      (Bb*Ll)      // 4096
#define NP1     8576
#define DTOFF   (INTER_ + CONVD_)   // 8448, tile-aligned (66*128)

// ---------------- static scratch ----------------
__device__ __half g_proj  [(size_t)MT*PROJ_];
__device__ float  g_dtraw [(size_t)MT*NH_];
__device__ __half g_xbc   [(size_t)MT*CONVD_];
__device__ __half g_y     [(size_t)MT*INTER_];
__device__ float  g_states[(size_t)Bb*NC_*NH_*HD_*ST_];
__device__ __half g_prev  [(size_t)Bb*NC_*NH_*HD_*ST_];
__device__ float  g_cum   [(size_t)Bb*NH_*Ll];
__device__ float  g_alast [(size_t)Bb*NH_*NC_];
__device__ float  g_P     [(size_t)Bb*NC_*CS_*CS_];
__device__ __half g_Af [(size_t)MT*INTER_];
__device__ __half g_W1 [(size_t)NP1*HIDDEN_];
__device__ __half g_W2 [(size_t)HIDDEN_*INTER_];

// ======================= warp-MMA helpers ====================
__device__ __forceinline__ uint32_t cvta_smem(const void* p) {
    uint32_t a;
    asm("{ .reg .u64 t; cvta.to.shared.u64 t, %1; cvt.u32.u64 %0, t; }"
        : "=r"(a) : "l"(p));
    return a;
}

__device__ __forceinline__ void ldsm4(uint32_t* r, uint32_t addr) {
    asm volatile("ldmatrix.sync.aligned.m8n8.x4.shared.b16 {%0,%1,%2,%3}, [%4];"
                 : "=r"(r[0]), "=r"(r[1]), "=r"(r[2]), "=r"(r[3]) : "r"(addr));
}

__device__ __forceinline__ void mma16816(float* c, const uint32_t* a,
                                         uint32_t b0, uint32_t b1) {
    asm volatile(
        "mma.sync.aligned.m16n8k16.row.col.f32.f16.f16.f32 "
        "{%0,%1,%2,%3}, {%4,%5,%6,%7}, {%8,%9}, {%0,%1,%2,%3};"
        : "+f"(c[0]), "+f"(c[1]), "+f"(c[2]), "+f"(c[3])
        : "r"(a[0]), "r"(a[1]), "r"(a[2]), "r"(a[3]), "r"(b0), "r"(b1));
}

__device__ __forceinline__ uint32_t swz(int row, int col) {
    return (uint32_t)(row * 128) + (uint32_t)(((col * 2) ^ ((row & 7) << 4)));
}

#define CPASYNC16(sa, ga) \
    asm volatile("cp.async.cg.shared.global [%0], [%1], 16;" :: "r"(sa), "l"(ga) : "memory")

// GEMM tiling: BM=128, BN=128, BK=64, 256 threads, 2 CTAs/SM, 3 stages
#define ATILEB 16384u
#define STAGEB 32768u
#define NSTG   3
#define GSMEM  (1024 + NSTG*32768)

// =========================================================================
// single-pass fp16 tensor-core GEMM: C = A*W^T + bias (templated output)
// =========================================================================
template<typename TOut>
__global__ __launch_bounds__(256, 2)
void tc_gemm_bias(
    const __half* __restrict__ A, const __half* __restrict__ W,
    const float* __restrict__ bias, TOut* __restrict__ C,
    float* __restrict__ dtsave, int N, int K)
{
    extern __shared__ __align__(128) char smem[];
    const int tid = threadIdx.x;
    const int lid = tid & 31, wid = tid >> 5;
    uint32_t sb = cvta_smem(smem);
    uint32_t tb = (sb + 1023u) & ~1023u;

    const size_t arow = (size_t)blockIdx.y * 128;
    const size_t brow = (size_t)blockIdx.x * 128;
    const int NCH = K >> 6;

    const int seg = tid & 7, r0 = tid >> 3;
    uint32_t so[4];
#pragma unroll
    for (int k = 0; k < 4; k++) {
        uint32_t off = (uint32_t)((r0 + 32 * k) * 128 + seg * 16);
        so[k] = off ^ ((off >> 3) & 0x70);
    }
    const __half* pA = A + (arow + r0) * (size_t)K + (seg << 3);
    const __half* pW = W + (brow + r0) * (size_t)K + (seg << 3);
    const size_t off32 = (size_t)32 * K;

#define LOAD_STAGE(s)                                                     \
    do {                                                                  \
        uint32_t stb_ = tb + (uint32_t)(s) * STAGEB;                      \
        CPASYNC16(stb_ + so[0], pA);                                      \
        CPASYNC16(stb_ + so[1], pA + off32);                              \
        CPASYNC16(stb_ + so[2], pA + 2 * off32);                          \
        CPASYNC16(stb_ + so[3], pA + 3 * off32);                          \
        CPASYNC16(stb_ + ATILEB + so[0], pW);                             \
        CPASYNC16(stb_ + ATILEB + so[1], pW + off32);                     \
        CPASYNC16(stb_ + ATILEB + so[2], pW + 2 * off32);                 \
        CPASYNC16(stb_ + ATILEB + so[3], pW + 3 * off32);                 \
        asm volatile("cp.async.commit_group;" ::: "memory");              \
        pA += 64; pW += 64;                                               \
    } while (0)

    const int wm = wid & 3, wn = wid >> 2;
    const int m0 = wm * 32, n0 = wn * 64;
    const int lr  = lid & 15;
    const int lkb = (lid >> 4) * 16;

    float acc[2][8][4];
#pragma unroll
    for (int mi = 0; mi < 2; mi++)
#pragma unroll
        for (int nj = 0; nj < 8; nj++)
#pragma unroll
            for (int q = 0; q < 4; q++) acc[mi][nj][q] = 0.f;

    uint32_t aoff[2], boff[4];
#pragma unroll
    for (int mi = 0; mi < 2; mi++) {
        int row = m0 + mi * 16 + lr;
        aoff[mi] = (uint32_t)(row * 128) + (uint32_t)(((row & 7) * 16) ^ lkb);
    }
#pragma unroll
    for (int ni = 0; ni < 4; ni++) {
        int row = n0 + ni * 16 + lr;
        boff[ni] = (uint32_t)(row * 128) + (uint32_t)(((row & 7) * 16) ^ lkb);
    }

    LOAD_STAGE(0);
    LOAD_STAGE(1);

    for (int c = 0; c < NCH; c++) {
        if (c + 1 < NCH) asm volatile("cp.async.wait_group 1;" ::: "memory");
        else             asm volatile("cp.async.wait_group 0;" ::: "memory");
        __syncthreads();
        if (c + 2 < NCH) LOAD_STAGE((c + 2) % NSTG);

        uint32_t stb = tb + (uint32_t)(c % NSTG) * STAGEB;
#pragma unroll
        for (int kk = 0; kk < 4; kk++) {
            uint32_t kx = (uint32_t)(kk * 32);
            uint32_t a_f[2][4];
#pragma unroll
            for (int mi = 0; mi < 2; mi++)
                ldsm4(a_f[mi], stb + (aoff[mi] ^ kx));
            uint32_t w_f[4][4];
#pragma unroll
            for (int ni = 0; ni < 4; ni++)
                ldsm4(w_f[ni], stb + ATILEB + (boff[ni] ^ kx));
#pragma unroll
            for (int mi = 0; mi < 2; mi++)
#pragma unroll
                for (int ni = 0; ni < 4; ni++) {
                    mma16816(acc[mi][2*ni],   a_f[mi], w_f[ni][0], w_f[ni][2]);
                    mma16816(acc[mi][2*ni+1], a_f[mi], w_f[ni][1], w_f[ni][3]);
                }
        }
    }

    const int er = lid >> 2;
    const int ec = (lid & 3) * 2;
#pragma unroll
    for (int mi = 0; mi < 2; mi++) {
        int grow0 = (int)arow + m0 + mi * 16 + er;
#pragma unroll
        for (int nj = 0; nj < 8; nj++) {
            int gcol = (int)brow + n0 + nj * 8 + ec;
            if (gcol + 1 < N) {
                float b0 = __ldg(&bias[gcol]), b1 = __ldg(&bias[gcol + 1]);
                float v00 = acc[mi][nj][0] + b0, v01 = acc[mi][nj][1] + b1;
                float v10 = acc[mi][nj][2] + b0, v11 = acc[mi][nj][3] + b1;
                if (sizeof(TOut) == 2) {
                    *(__half2*)&C[(size_t)grow0 * N + gcol] =
                        __floats2half2_rn(v00, v01);
                    *(__half2*)&C[(size_t)(grow0 + 8) * N + gcol] =
                        __floats2half2_rn(v10, v11);
                } else {
                    *(float2*)&C[(size_t)grow0 * N + gcol] = make_float2(v00, v01);
                    *(float2*)&C[(size_t)(grow0 + 8) * N + gcol] = make_float2(v10, v11);
                }
                if (dtsave && gcol >= DTOFF) {
                    int dcol = gcol - DTOFF;
                    *(float2*)&dtsave[(size_t)grow0 * NH_ + dcol] =
                        make_float2(v00, v01);
                    *(float2*)&dtsave[(size_t)(grow0 + 8) * NH_ + dcol] =
                        make_float2(v10, v11);
                }
            } else if (gcol < N) {
                float b0 = __ldg(&bias[gcol]);
                float v0 = acc[mi][nj][0] + b0, v1 = acc[mi][nj][2] + b0;
                if (sizeof(TOut) == 2) {
                    C[(size_t)grow0 * N + gcol] = (TOut)__float2half_rn(v0);
                    C[(size_t)(grow0 + 8) * N + gcol] = (TOut)__float2half_rn(v1);
                } else {
                    C[(size_t)grow0 * N + gcol] = (TOut)v0;
                    C[(size_t)(grow0 + 8) * N + gcol] = (TOut)v1;
                }
                if (dtsave && gcol >= DTOFF) {
                    int dcol = gcol - DTOFF;
                    dtsave[(size_t)grow0 * NH_ + dcol] = v0;
                    dtsave[(size_t)(grow0 + 8) * NH_ + dcol] = v1;
                }
            }
        }
    }
#undef LOAD_STAGE
}

// ---------------- fp32 -> fp16 conversions ---------------------------------
__global__ void cvt_fp16_kernel(const float4* __restrict__ src,
                                __half2* __restrict__ dst, size_t n4)
{
    size_t i = (size_t)blockIdx.x * blockDim.x + threadIdx.x;
    if (i >= n4) return;
    float4 v = src[i];
    dst[2*i]   = __floats2half2_rn(v.x, v.y);
    dst[2*i+1] = __floats2half2_rn(v.z, v.w);
}

__global__ void cvt_fp16_pad_kernel(const float4* __restrict__ src,
                                    __half2* __restrict__ dst,
                                    size_t n4v, size_t n4t)
{
    size_t i = (size_t)blockIdx.x * blockDim.x + threadIdx.x;
    if (i >= n4t) return;
    float4 v = (i < n4v) ? src[i] : make_float4(0.f, 0.f, 0.f, 0.f);
    dst[2*i]   = __floats2half2_rn(v.x, v.y);
    dst[2*i+1] = __floats2half2_rn(v.z, v.w);
}

// ---------------- causal depthwise conv (K=4) + SiLU -> fp16 ---------------
__global__ __launch_bounds__(256) void conv_silu_kernel(
    const __half* __restrict__ proj, const float* __restrict__ cw,
    __half* __restrict__ xbc)
{
    const int ch = blockIdx.x * 256 + threadIdx.x;
    const int b  = blockIdx.z;
    const int t0 = blockIdx.y * 128;
    const __half* col = proj + (size_t)b * Ll * PROJ_ + INTER_ + ch;
    const float4 w = *(const float4*)&cw[ch * 4];
    float xm3 = 0.f, xm2 = 0.f, xm1 = 0.f;
    if (t0 > 0) {
        xm3 = __half2float(col[(size_t)(t0 - 3) * PROJ_]);
        xm2 = __half2float(col[(size_t)(t0 - 2) * PROJ_]);
        xm1 = __half2float(col[(size_t)(t0 - 1) * PROJ_]);
    }
    __half* dst = xbc + ((size_t)(b * Ll + t0)) * CONVD_ + ch;
    const __half* srcp = col + (size_t)t0 * PROJ_;
#pragma unroll 4
    for (int k = 0; k < 128; k++) {
        float xc = __half2float(srcp[(size_t)k * PROJ_]);
        float acc = w.x * xm3 + w.y * xm2 + w.z * xm1 + w.w * xc;
        float sg = 1.f / (1.f + __expf(-acc));
        dst[(size_t)k * CONVD_] = __float2half_rn(acc * sg);
        xm3 = xm2; xm2 = xm1; xm1 = xc;
    }
}

// ---------------- P = C * B^T (fp32 acc, fp16 inputs) ----------------------
__device__ __constant__ int c_PI[10] = {0,1,1,2,2,2,3,3,3,3};
__device__ __constant__ int c_PJ[10] = {0,0,1,0,1,2,0,1,2,3};

__global__ __launch_bounds__(256, 3) void pmat_kernel(
    const __half* __restrict__ xbc, float* __restrict__ P)
{
    const int p = blockIdx.x, c = blockIdx.y, b = blockIdx.z;
    const int i = c_PI[p], j = c_PJ[p];
    const int tid = threadIdx.x;
    extern __shared__ float sm[];
    float* CsT = sm;              // [128][68]
    float* BsT = CsT + 128 * 68;  // [128][68]
    const size_t rowbase = (size_t)(b * Ll + c * CS_);

    for (int idx = tid; idx < 64 * 128; idx += 256) {
        int tl = idx >> 7, n = idx & 127;
        CsT[n * 68 + tl] =
            __half2float(xbc[(rowbase + i * 64 + tl) * CONVD_ + (INTER_ + ST_) + n]);
        BsT[n * 68 + tl] =
            __half2float(xbc[(rowbase + j * 64 + tl) * CONVD_ + INTER_ + n]);
    }
    __syncthreads();

    const int tx = tid & 15, ty = tid >> 4;
    const int t0 = ty * 4, s0 = tx * 4;
    float pf[4][4];
#pragma unroll
    for (int r = 0; r < 4; r++)
#pragma unroll
        for (int q = 0; q < 4; q++) pf[r][q] = 0.f;
    for (int n = 0; n < 128; n++) {
        float4 c4 = *(const float4*)&CsT[n * 68 + t0];
        float4 b4 = *(const float4*)&BsT[n * 68 + s0];
        float cr[4] = {c4.x, c4.y, c4.z, c4.w};
        float br[4] = {b4.x, b4.y, b4.z, b4.w};
#pragma unroll
        for (int r = 0; r < 4; r++)
#pragma unroll
            for (int q = 0; q < 4; q++)
                pf[r][q] = fmaf(cr[r], br[q], pf[r][q]);
    }
    float* dst = P + ((size_t)(b * NC_ + c) * CS_) * CS_;
#pragma unroll
    for (int r = 0; r < 4; r++) {
        float4 o = {pf[r][0], pf[r][1], pf[r][2], pf[r][3]};
        *(float4*)&dst[(size_t)(i * 64 + t0 + r) * CS_ + j * 64 + s0] = o;
    }
}

// ---------------- intra-chunk scan: fp16 mma, x tiles cached ----------------
__global__ __launch_bounds__(256) void scan_intra_kernel(
    const float* __restrict__ dtraw, const __half* __restrict__ xbc,
    const float* __restrict__ gP,
    const float* __restrict__ dt_bias, const float* __restrict__ A_log,
    __half* __restrict__ ydiag, float* __restrict__ states,
    float* __restrict__ cumg, float* __restrict__ alast)
{
    const int h = blockIdx.x, c = blockIdx.y, b = blockIdx.z;
    const int tid = threadIdx.x;
    extern __shared__ __align__(128) char smem[];
    char* PwS  = smem;
    char* xAll = smem + 8192;
    char* BwS  = smem + 40960;
    float* dsh   = (float*)(smem + 57344);
    float* cum   = dsh + 256;
    float* wlast = cum + 256;
    float* Esh   = wlast + 256;
    uint32_t sb = cvta_smem(smem);

    {
        float Ah = -__expf(A_log[h]);
        float v = dtraw[(size_t)(b * Ll + c * CS_ + tid) * NH_ + h] + dt_bias[h];
        float dtv = (v > 20.f) ? v : log1pf(__expf(v));
        dsh[tid] = dtv;
        cum[tid] = Ah * dtv;
    }
    __syncthreads();
    for (int off = 1; off < 256; off <<= 1) {
        float add = (tid >= off) ? cum[tid - off] : 0.f;
        __syncthreads();
        cum[tid] += add;
        __syncthreads();
    }
    cumg[(size_t)(b * NH_ + h) * Ll + c * CS_ + tid] = cum[tid];
    if (tid == 255) alast[(b * NH_ + h) * NC_ + c] = cum[255];
    wlast[tid] = __expf(cum[255] - cum[tid]);

    const size_t rowbase = (size_t)(b * Ll + c * CS_);
    const int sfix = tid & 63, rfix = tid >> 6;

#pragma unroll
    for (int jt = 0; jt < 4; jt++) {
        char* xt = xAll + jt * 8192;
        const int p = sfix;
#pragma unroll
        for (int k = 0; k < 16; k++) {
            int s = rfix + 4 * k;
            float v = __half2float(
                          xbc[(rowbase + jt * 64 + s) * CONVD_ + h * HD_ + p])
                      * dsh[jt * 64 + s];
            *(__half*)(xt + swz(p, s)) = __float2half_rn(v);
        }
    }

    const int lid = tid & 31, wid = tid >> 5;
    const int tm = (wid & 3) * 16;
    const int pn = (wid >> 2) * 32;
    const int nn = (wid >> 2) * 64;
    const int lr = lid & 15;
    const int lkb = (lid >> 4) * 16;

    uint32_t roff;
    {
        int row = tm + lr;
        roff = (uint32_t)(row * 128) + (uint32_t)(((row & 7) * 16) ^ lkb);
    }
    uint32_t boffX[2], boffB[4];
#pragma unroll
    for (int ni = 0; ni < 2; ni++) {
        int row = pn + ni * 16 + lr;
        boffX[ni] = (uint32_t)(row * 128) + (uint32_t)(((row & 7) * 16) ^ lkb);
    }
#pragma unroll
    for (int ni = 0; ni < 4; ni++) {
        int row = nn + ni * 16 + lr;
        boffB[ni] = (uint32_t)(row * 128) + (uint32_t)(((row & 7) * 16) ^ lkb);
    }

    float stacc[8][4];
#pragma unroll
    for (int nj = 0; nj < 8; nj++)
#pragma unroll
        for (int q = 0; q < 4; q++) stacc[nj][q] = 0.f;

    const float* Pblk = gP + ((size_t)(b * NC_ + c) * CS_) * CS_;

    for (int i = 0; i < 4; i++) {
        if (tid < 64) Esh[tid] = __expf(cum[i * 64 + tid] - cum[i * 64]);
        float yacc[4][4];
#pragma unroll
        for (int nj = 0; nj < 4; nj++)
#pragma unroll
            for (int q = 0; q < 4; q++) yacc[nj][q] = 0.f;

        for (int j = 0; j <= i; j++) {
            __syncthreads();
            if (j == i) {
                const int n = tid & 127;
#pragma unroll
                for (int k = 0; k < 32; k++) {
                    int s = (tid >> 7) + 2 * k;
                    float v = __half2float(
                                  xbc[(rowbase + i * 64 + s) * CONVD_ + INTER_ + n])
                              * wlast[i * 64 + s];
                    *(__half*)(BwS + swz(n, s)) = __float2half_rn(v);
                }
                const int s = sfix;
#pragma unroll
                for (int k = 0; k < 16; k++) {
                    int tl = rfix + 4 * k;
                    float w = (s <= tl) ? __expf(cum[i*64 + tl] - cum[i*64 + s]) : 0.f;
                    *(__half*)(PwS + swz(tl, s)) =
                        __float2half_rn(Pblk[(size_t)(i*64 + tl) * CS_ + i*64 + s] * w);
                }
            } else {
                const int s = sfix;
                float rs = __expf(cum[i * 64] - cum[j * 64 + s]);
#pragma unroll
                for (int k = 0; k < 16; k++) {
                    int tl = rfix + 4 * k;
                    *(__half*)(PwS + swz(tl, s)) =
                        __float2half_rn(Pblk[(size_t)(i*64 + tl) * CS_ + j*64 + s]
                                        * Esh[tl] * rs);
                }
            }
            __syncthreads();
            const uint32_t pwb = sb, xjb = sb + 8192u + (uint32_t)j * 8192u;
#pragma unroll
            for (int ks = 0; ks < 4; ks++) {
                uint32_t kx = (uint32_t)(ks * 32);
                uint32_t a[4];
                ldsm4(a, pwb + (roff ^ kx));
#pragma unroll
                for (int ni = 0; ni < 2; ni++) {
                    uint32_t bf[4];
                    ldsm4(bf, xjb + (boffX[ni] ^ kx));
                    mma16816(yacc[2*ni],   a, bf[0], bf[2]);
                    mma16816(yacc[2*ni+1], a, bf[1], bf[3]);
                }
            }
            if (j == i) {
                const uint32_t bwb = sb + 40960u;
                const uint32_t xib = sb + 8192u + (uint32_t)i * 8192u;
#pragma unroll
                for (int ks = 0; ks < 4; ks++) {
                    uint32_t kx = (uint32_t)(ks * 32);
                    uint32_t a[4];
                    ldsm4(a, xib + (roff ^ kx));
#pragma unroll
                    for (int ni = 0; ni < 4; ni++) {
                        uint32_t bf[4];
                        ldsm4(bf, bwb + (boffB[ni] ^ kx));
                        mma16816(stacc[2*ni],   a, bf[0], bf[2]);
                        mma16816(stacc[2*ni+1], a, bf[1], bf[3]);
                    }
                }
            }
        }
        {
            const int er = lid >> 2, ec = (lid & 3) * 2;
#pragma unroll
            for (int nj = 0; nj < 4; nj++) {
                int p = pn + nj * 8 + ec;
                size_t tg = rowbase + i * 64 + tm + er;
                *(__half2*)&ydiag[(tg * NH_ + h) * HD_ + p] =
                    __floats2half2_rn(yacc[nj][0], yacc[nj][1]);
                *(__half2*)&ydiag[((tg + 8) * NH_ + h) * HD_ + p] =
                    __floats2half2_rn(yacc[nj][2], yacc[nj][3]);
            }
        }
    }
    {
        const int er = lid >> 2, ec = (lid & 3) * 2;
        size_t base = ((size_t)((b * NC_ + c) * NH_ + h)) * HD_;
#pragma unroll
        for (int nj = 0; nj < 8; nj++) {
            int p = tm + er, n = nn + nj * 8 + ec;
            *(float2*)&states[(base + p) * ST_ + n] =
                make_float2(stacc[nj][0], stacc[nj][1]);
            *(float2*)&states[(base + p + 8) * ST_ + n] =
                make_float2(stacc[nj][2], stacc[nj][3]);
        }
    }
}

// ---------------- inter-chunk recurrence (prev -> fp16) --------------------
__global__ void interchunk_kernel(const float* __restrict__ states,
                                  const float* __restrict__ alast,
                                  __half* __restrict__ prev)
{
    int bh = blockIdx.x;
    int b = bh >> 6, h = bh & 63;
    float dec[NC_];
#pragma unroll
    for (int c = 0; c < NC_; c++)
        dec[c] = __expf(alast[(b * NH_ + h) * NC_ + c]);
    for (int e = threadIdx.x; e < HD_ * ST_; e += 256) {
        float run = 0.f;
#pragma unroll
        for (int c = 0; c < NC_; c++) {
            size_t idx = ((size_t)((b * NC_ + c) * NH_ + h)) * (HD_ * ST_) + e;
            prev[idx] = __float2half_rn(run);
            run = fmaf(run, dec[c] - 1.f, run);
            run = run + states[idx];
        }
    }
}

// ---------------- Y_off via fp16 mma + D-skip (fp16 y RMW) ------------------
__global__ __launch_bounds__(256) void scan_off_kernel(
    const __half* __restrict__ xbc, const float* __restrict__ cumg,
    const __half* __restrict__ prev, const float* __restrict__ Dv,
    __half* __restrict__ y)
{
    const int h = blockIdx.x, c = blockIdx.y, b = blockIdx.z;
    const int tid = threadIdx.x;
    extern __shared__ __align__(128) char smem[];
    char* CsS   = smem;
    char* prevS = smem + 16384;
    float* esh  = (float*)(smem + 32768);
    uint32_t sb = cvta_smem(smem);

    size_t sbase = ((size_t)((b * NC_ + c) * NH_ + h)) * (HD_ * ST_);
    for (int idx = tid; idx < 64 * 128; idx += 256) {
        int p = idx >> 7, n = idx & 127;
        *(__half*)(prevS + (n >> 6) * 8192 + swz(p, n & 63)) = prev[sbase + idx];
    }
    esh[tid] = __expf(cumg[(size_t)(b * NH_ + h) * Ll + c * CS_ + tid]);
    const float Dh = Dv[h];
    const size_t rowbase = (size_t)(b * Ll + c * CS_);

    const int lid = tid & 31, wid = tid >> 5;
    const int tm = (wid & 3) * 16, pn = (wid >> 2) * 32;
    const int lr = lid & 15;
    const int lkb = (lid >> 4) * 16;
    uint32_t aoffC, boffP[2];
    {
        int row = tm + lr;
        aoffC = (uint32_t)(row * 128) + (uint32_t)(((row & 7) * 16) ^ lkb);
    }
#pragma unroll
    for (int ni = 0; ni < 2; ni++) {
        int row = pn + ni * 16 + lr;
        boffP[ni] = (uint32_t)(row * 128) + (uint32_t)(((row & 7) * 16) ^ lkb);
    }

    for (int ti = 0; ti < 4; ti++) {
        __syncthreads();
        for (int idx = tid; idx < 64 * 128; idx += 256) {
            int t = idx >> 7, n = idx & 127;
            *(__half*)(CsS + (n >> 6) * 8192 + swz(t, n & 63)) =
                xbc[(rowbase + ti * 64 + t) * CONVD_ + (INTER_ + ST_) + n];
        }
        __syncthreads();
        float acc[4][4];
#pragma unroll
        for (int nj = 0; nj < 4; nj++)
#pragma unroll
            for (int q = 0; q < 4; q++) acc[nj][q] = 0.f;
#pragma unroll
        for (int kt = 0; kt < 2; kt++) {
            uint32_t cb = sb + (uint32_t)kt * 8192u;
            uint32_t pb = sb + 16384u + (uint32_t)kt * 8192u;
#pragma unroll
            for (int ks = 0; ks < 4; ks++) {
                uint32_t kx = (uint32_t)(ks * 32);
                uint32_t a[4];
                ldsm4(a, cb + (aoffC ^ kx));
#pragma unroll
                for (int ni = 0; ni < 2; ni++) {
                    uint32_t bf[4];
                    ldsm4(bf, pb + (boffP[ni] ^ kx));
                    mma16816(acc[2*ni],   a, bf[0], bf[2]);
                    mma16816(acc[2*ni+1], a, bf[1], bf[3]);
                }
            }
        }
        const int er = lid >> 2, ec = (lid & 3) * 2;
#pragma unroll
        for (int nj = 0; nj < 4; nj++) {
            int p = pn + nj * 8 + ec;
            int t0g = ti * 64 + tm + er;
            size_t tg = rowbase + t0g;
            float e0 = esh[t0g], e1 = esh[t0g + 8];
            __half2* yp0 = (__half2*)&y[(tg * NH_ + h) * HD_ + p];
            __half2* yp1 = (__half2*)&y[((tg + 8) * NH_ + h) * HD_ + p];
            float2 yv0 = __half22float2(*yp0), yv1 = __half22float2(*yp1);
            float2 xv0 = __half22float2(
                *(const __half2*)&xbc[tg * CONVD_ + h * HD_ + p]);
            float2 xv1 = __half22float2(
                *(const __half2*)&xbc[(tg + 8) * CONVD_ + h * HD_ + p]);
            yv0.x += acc[nj][0] * e0 + Dh * xv0.x;
            yv0.y += acc[nj][1] * e0 + Dh * xv0.y;
            yv1.x += acc[nj][2] * e1 + Dh * xv1.x;
            yv1.y += acc[nj][3] * e1 + Dh * xv1.y;
            *yp0 = __floats2half2_rn(yv0.x, yv0.y);
            *yp1 = __floats2half2_rn(yv1.x, yv1.y);
        }
    }
}

// ---------------- gated RMSNorm -> fp16 A for GEMM2 ------------------------
__global__ __launch_bounds__(256) void gated_norm_kernel(
    const __half* __restrict__ proj, const __half* __restrict__ y,
    const float* __restrict__ nw, __half* __restrict__ gf)
{
    int row = blockIdx.x;
    int tid = threadIdx.x;
    float gv[16];
    float ss = 0.f;
    const __half* yr = y + (size_t)row * INTER_;
    const __half* gr = proj + (size_t)row * PROJ_;
#pragma unroll
    for (int k = 0; k < 16; k++) {
        int idx = tid + k * 256;
        float gt = __half2float(gr[idx]);
        float s = 1.f / (1.f + __expf(-gt));
        float v = __half2float(yr[idx]) * gt * s;
        gv[k] = v;
        ss = fmaf(v, v, ss);
    }
    __shared__ float red[256];
    red[tid] = ss;
    __syncthreads();
    for (int off = 128; off > 0; off >>= 1) {
        if (tid < off) red[tid] += red[tid + off];
        __syncthreads();
    }
    float scale = rsqrtf(red[0] / (float)INTER_ + 1e-5f);
#pragma unroll
    for (int k = 0; k < 16; k++) {
        int idx = tid + k * 256;
        gf[(size_t)row * INTER_ + idx] = __float2half_rn(gv[k] * scale * nw[idx]);
    }
}

// ---------------- launch ----------------------------------------------------
extern "C" void kernel_launch(void* const* d_in, const int* in_sizes, int n_in,
                              void* d_out, int out_size)
{
    const float* hidden  = (const float*)d_in[0];
    const float* in_w    = (const float*)d_in[1];
    const float* in_b    = (const float*)d_in[2];
    const float* conv_w  = (const float*)d_in[3];
    const float* dt_bias = (const float*)d_in[4];
    const float* A_log   = (const float*)d_in[5];
    const float* Dv      = (const float*)d_in[6];
    const float* norm_w  = (const float*)d_in[7];
    const float* out_w   = (const float*)d_in[8];
    const float* out_b   = (const float*)d_in[9];
    float* out = (float*)d_out;

    float *dtraw, *states, *cum, *al, *Pm;
    __half *proj, *xbc, *y, *prev, *Af, *W1, *W2;
    cudaGetSymbolAddress((void**)&proj,   g_proj);
    cudaGetSymbolAddress((void**)&dtraw,  g_dtraw);
    cudaGetSymbolAddress((void**)&xbc,    g_xbc);
    cudaGetSymbolAddress((void**)&y,      g_y);
    cudaGetSymbolAddress((void**)&states, g_states);
    cudaGetSymbolAddress((void**)&prev,   g_prev);
    cudaGetSymbolAddress((void**)&cum,    g_cum);
    cudaGetSymbolAddress((void**)&al,     g_alast);
    cudaGetSymbolAddress((void**)&Pm,     g_P);
    cudaGetSymbolAddress((void**)&Af,     g_Af);
    cudaGetSymbolAddress((void**)&W1,     g_W1);
    cudaGetSymbolAddress((void**)&W2,     g_W2);

    const int SMEM_PMAT  = (128 * 68 * 2) * 4;
    const int SMEM_INTRA = 57344 + (256 * 3 + 64) * 4;
    const int SMEM_OFF   = 32768 + 256 * 4;
    cudaFuncSetAttribute(pmat_kernel,
                         cudaFuncAttributeMaxDynamicSharedMemorySize, SMEM_PMAT);
    cudaFuncSetAttribute(scan_intra_kernel,
                         cudaFuncAttributeMaxDynamicSharedMemorySize, SMEM_INTRA);
    cudaFuncSetAttribute(scan_off_kernel,
                         cudaFuncAttributeMaxDynamicSharedMemorySize, SMEM_OFF);
    cudaFuncSetAttribute(tc_gemm_bias<__half>,
                         cudaFuncAttributeMaxDynamicSharedMemorySize, GSMEM);
    cudaFuncSetAttribute(tc_gemm_bias<float>,
                         cudaFuncAttributeMaxDynamicSharedMemorySize, GSMEM);

    // 0. fp16 conversions
    {
        size_t n4 = (size_t)MT * HIDDEN_ / 4;
        cvt_fp16_kernel<<<(int)((n4 + 255) / 256), 256>>>(
            (const float4*)hidden, (__half2*)Af, n4);
        size_t n4v = (size_t)PROJ_ * HIDDEN_ / 4, n4t = (size_t)NP1 * HIDDEN_ / 4;
        cvt_fp16_pad_kernel<<<(int)((n4t + 255) / 256), 256>>>(
            (const float4*)in_w, (__half2*)W1, n4v, n4t);
        n4 = (size_t)HIDDEN_ * INTER_ / 4;
        cvt_fp16_kernel<<<(int)((n4 + 255) / 256), 256>>>(
            (const float4*)out_w, (__half2*)W2, n4);
    }

    // 1. in_proj GEMM + bias -> fp16 proj + fp32 dt side-channel
    tc_gemm_bias<__half><<<dim3(NP1 / 128, MT / 128), 256, GSMEM>>>(
        Af, W1, in_b, proj, dtraw, PROJ_, HIDDEN_);

    // 2. causal depthwise conv + SiLU -> fp16 xbc
    conv_silu_kernel<<<dim3(CONVD_ / 256, Ll / 128, Bb), 256>>>(proj, conv_w, xbc);

    // 2b. shared P = C * B^T per (b, chunk)
    pmat_kernel<<<dim3(10, NC_, Bb), 256, SMEM_PMAT>>>(xbc, Pm);

    // 3. intra-chunk scan (fp16 mma, fp32 dt)
    scan_intra_kernel<<<dim3(NH_, NC_, Bb), 256, SMEM_INTRA>>>(
        dtraw, xbc, Pm, dt_bias, A_log, y, states, cum, al);

    // 4. inter-chunk recurrence -> fp16 prev
    interchunk_kernel<<<Bb * NH_, 256>>>(states, al, prev);

    // 5. inter-chunk output contribution + D skip
    scan_off_kernel<<<dim3(NH_, NC_, Bb), 256, SMEM_OFF>>>(xbc, cum, prev, Dv, y);

    // 6. gated RMSNorm -> fp16 A for GEMM2
    gated_norm_kernel<<<MT, 256>>>(proj, y, norm_w, Af);

    // 7. out_proj GEMM + bias -> fp32 out
    tc_gemm_bias<float><<<dim3(HIDDEN_ / 128, MT / 128), 256, GSMEM>>>(
        Af, W2, out_b, out, nullptr, HIDDEN_, INTER_);
}

// round 15
// speedup vs baseline: 1.0245x; 1.0245x over previous
#include <cuda_runtime.h>
#include <cuda_bf16.h>
#include <cuda_fp16.h>
#include <math.h>
#include <cstdint>

#define Bb      2
#define Ll      2048
#define HIDDEN_ 2048
#define PROJ_   8512
#define INTER_  4096
#define CONVD_  4352
#define NH_     64
#define HD_     64
#define ST_     128
#define NC_     8
#define CS_     256
#define MT      (Bb*Ll)      // 4096
#define NP1     8576
#define DTOFF   (INTER_ + CONVD_)   // 8448, tile-aligned (66*128)

// ---------------- static scratch ----------------
__device__ __half g_proj  [(size_t)MT*PROJ_];
__device__ float  g_dtraw [(size_t)MT*NH_];
__device__ __half g_xbc   [(size_t)MT*CONVD_];
__device__ __half g_y     [(size_t)MT*INTER_];
__device__ float  g_states[(size_t)Bb*NC_*NH_*HD_*ST_];
__device__ __half g_prev  [(size_t)Bb*NC_*NH_*HD_*ST_];
__device__ float  g_cum   [(size_t)Bb*NH_*Ll];
__device__ float  g_alast [(size_t)Bb*NH_*NC_];
__device__ __half g_P     [(size_t)Bb*NC_*CS_*CS_];     // fp16 now
__device__ __half g_Af [(size_t)MT*INTER_];
__device__ __half g_W1 [(size_t)NP1*HIDDEN_];
__device__ __half g_W2 [(size_t)HIDDEN_*INTER_];

// ======================= warp-MMA helpers ====================
__device__ __forceinline__ uint32_t cvta_smem(const void* p) {
    uint32_t a;
    asm("{ .reg .u64 t; cvta.to.shared.u64 t, %1; cvt.u32.u64 %0, t; }"
        : "=r"(a) : "l"(p));
    return a;
}

__device__ __forceinline__ void ldsm4(uint32_t* r, uint32_t addr) {
    asm volatile("ldmatrix.sync.aligned.m8n8.x4.shared.b16 {%0,%1,%2,%3}, [%4];"
                 : "=r"(r[0]), "=r"(r[1]), "=r"(r[2]), "=r"(r[3]) : "r"(addr));
}

__device__ __forceinline__ void mma16816(float* c, const uint32_t* a,
                                         uint32_t b0, uint32_t b1) {
    asm volatile(
        "mma.sync.aligned.m16n8k16.row.col.f32.f16.f16.f32 "
        "{%0,%1,%2,%3}, {%4,%5,%6,%7}, {%8,%9}, {%0,%1,%2,%3};"
        : "+f"(c[0]), "+f"(c[1]), "+f"(c[2]), "+f"(c[3])
        : "r"(a[0]), "r"(a[1]), "r"(a[2]), "r"(a[3]), "r"(b0), "r"(b1));
}

__device__ __forceinline__ uint32_t swz(int row, int col) {
    return (uint32_t)(row * 128) + (uint32_t)(((col * 2) ^ ((row & 7) << 4)));
}

#define CPASYNC16(sa, ga) \
    asm volatile("cp.async.cg.shared.global [%0], [%1], 16;" :: "r"(sa), "l"(ga) : "memory")

// GEMM tiling: BM=128, BN=128, BK=64, 256 threads, 2 CTAs/SM, 3 stages
#define ATILEB 16384u
#define STAGEB 32768u
#define NSTG   3
#define GSMEM  (1024 + NSTG*32768)

// =========================================================================
// single-pass fp16 tensor-core GEMM: C = A*W^T + bias (templated output)
// =========================================================================
template<typename TOut>
__global__ __launch_bounds__(256, 2)
void tc_gemm_bias(
    const __half* __restrict__ A, const __half* __restrict__ W,
    const float* __restrict__ bias, TOut* __restrict__ C,
    float* __restrict__ dtsave, int N, int K)
{
    extern __shared__ __align__(128) char smem[];
    const int tid = threadIdx.x;
    const int lid = tid & 31, wid = tid >> 5;
    uint32_t sb = cvta_smem(smem);
    uint32_t tb = (sb + 1023u) & ~1023u;

    const size_t arow = (size_t)blockIdx.y * 128;
    const size_t brow = (size_t)blockIdx.x * 128;
    const int NCH = K >> 6;

    const int seg = tid & 7, r0 = tid >> 3;
    uint32_t so[4];
#pragma unroll
    for (int k = 0; k < 4; k++) {
        uint32_t off = (uint32_t)((r0 + 32 * k) * 128 + seg * 16);
        so[k] = off ^ ((off >> 3) & 0x70);
    }
    const __half* pA = A + (arow + r0) * (size_t)K + (seg << 3);
    const __half* pW = W + (brow + r0) * (size_t)K + (seg << 3);
    const size_t off32 = (size_t)32 * K;

#define LOAD_STAGE(s)                                                     \
    do {                                                                  \
        uint32_t stb_ = tb + (uint32_t)(s) * STAGEB;                      \
        CPASYNC16(stb_ + so[0], pA);                                      \
        CPASYNC16(stb_ + so[1], pA + off32);                              \
        CPASYNC16(stb_ + so[2], pA + 2 * off32);                          \
        CPASYNC16(stb_ + so[3], pA + 3 * off32);                          \
        CPASYNC16(stb_ + ATILEB + so[0], pW);                             \
        CPASYNC16(stb_ + ATILEB + so[1], pW + off32);                     \
        CPASYNC16(stb_ + ATILEB + so[2], pW + 2 * off32);                 \
        CPASYNC16(stb_ + ATILEB + so[3], pW + 3 * off32);                 \
        asm volatile("cp.async.commit_group;" ::: "memory");              \
        pA += 64; pW += 64;                                               \
    } while (0)

    const int wm = wid & 3, wn = wid >> 2;
    const int m0 = wm * 32, n0 = wn * 64;
    const int lr  = lid & 15;
    const int lkb = (lid >> 4) * 16;

    float acc[2][8][4];
#pragma unroll
    for (int mi = 0; mi < 2; mi++)
#pragma unroll
        for (int nj = 0; nj < 8; nj++)
#pragma unroll
            for (int q = 0; q < 4; q++) acc[mi][nj][q] = 0.f;

    uint32_t aoff[2], boff[4];
#pragma unroll
    for (int mi = 0; mi < 2; mi++) {
        int row = m0 + mi * 16 + lr;
        aoff[mi] = (uint32_t)(row * 128) + (uint32_t)(((row & 7) * 16) ^ lkb);
    }
#pragma unroll
    for (int ni = 0; ni < 4; ni++) {
        int row = n0 + ni * 16 + lr;
        boff[ni] = (uint32_t)(row * 128) + (uint32_t)(((row & 7) * 16) ^ lkb);
    }

    LOAD_STAGE(0);
    LOAD_STAGE(1);

    for (int c = 0; c < NCH; c++) {
        if (c + 1 < NCH) asm volatile("cp.async.wait_group 1;" ::: "memory");
        else             asm volatile("cp.async.wait_group 0;" ::: "memory");
        __syncthreads();
        if (c + 2 < NCH) LOAD_STAGE((c + 2) % NSTG);

        uint32_t stb = tb + (uint32_t)(c % NSTG) * STAGEB;
#pragma unroll
        for (int kk = 0; kk < 4; kk++) {
            uint32_t kx = (uint32_t)(kk * 32);
            uint32_t a_f[2][4];
#pragma unroll
            for (int mi = 0; mi < 2; mi++)
                ldsm4(a_f[mi], stb + (aoff[mi] ^ kx));
            uint32_t w_f[4][4];
#pragma unroll
            for (int ni = 0; ni < 4; ni++)
                ldsm4(w_f[ni], stb + ATILEB + (boff[ni] ^ kx));
#pragma unroll
            for (int mi = 0; mi < 2; mi++)
#pragma unroll
                for (int ni = 0; ni < 4; ni++) {
                    mma16816(acc[mi][2*ni],   a_f[mi], w_f[ni][0], w_f[ni][2]);
                    mma16816(acc[mi][2*ni+1], a_f[mi], w_f[ni][1], w_f[ni][3]);
                }
        }
    }

    const int er = lid >> 2;
    const int ec = (lid & 3) * 2;
#pragma unroll
    for (int mi = 0; mi < 2; mi++) {
        int grow0 = (int)arow + m0 + mi * 16 + er;
#pragma unroll
        for (int nj = 0; nj < 8; nj++) {
            int gcol = (int)brow + n0 + nj * 8 + ec;
            if (gcol + 1 < N) {
                float b0 = __ldg(&bias[gcol]), b1 = __ldg(&bias[gcol + 1]);
                float v00 = acc[mi][nj][0] + b0, v01 = acc[mi][nj][1] + b1;
                float v10 = acc[mi][nj][2] + b0, v11 = acc[mi][nj][3] + b1;
                if (sizeof(TOut) == 2) {
                    *(__half2*)&C[(size_t)grow0 * N + gcol] =
                        __floats2half2_rn(v00, v01);
                    *(__half2*)&C[(size_t)(grow0 + 8) * N + gcol] =
                        __floats2half2_rn(v10, v11);
                } else {
                    *(float2*)&C[(size_t)grow0 * N + gcol] = make_float2(v00, v01);
                    *(float2*)&C[(size_t)(grow0 + 8) * N + gcol] = make_float2(v10, v11);
                }
                if (dtsave && gcol >= DTOFF) {
                    int dcol = gcol - DTOFF;
                    *(float2*)&dtsave[(size_t)grow0 * NH_ + dcol] =
                        make_float2(v00, v01);
                    *(float2*)&dtsave[(size_t)(grow0 + 8) * NH_ + dcol] =
                        make_float2(v10, v11);
                }
            } else if (gcol < N) {
                float b0 = __ldg(&bias[gcol]);
                float v0 = acc[mi][nj][0] + b0, v1 = acc[mi][nj][2] + b0;
                if (sizeof(TOut) == 2) {
                    C[(size_t)grow0 * N + gcol] = (TOut)__float2half_rn(v0);
                    C[(size_t)(grow0 + 8) * N + gcol] = (TOut)__float2half_rn(v1);
                } else {
                    C[(size_t)grow0 * N + gcol] = (TOut)v0;
                    C[(size_t)(grow0 + 8) * N + gcol] = (TOut)v1;
                }
                if (dtsave && gcol >= DTOFF) {
                    int dcol = gcol - DTOFF;
                    dtsave[(size_t)grow0 * NH_ + dcol] = v0;
                    dtsave[(size_t)(grow0 + 8) * NH_ + dcol] = v1;
                }
            }
        }
    }
#undef LOAD_STAGE
}

// ---------------- fp32 -> fp16 conversions ---------------------------------
__global__ void cvt_fp16_kernel(const float4* __restrict__ src,
                                __half2* __restrict__ dst, size_t n4)
{
    size_t i = (size_t)blockIdx.x * blockDim.x + threadIdx.x;
    if (i >= n4) return;
    float4 v = src[i];
    dst[2*i]   = __floats2half2_rn(v.x, v.y);
    dst[2*i+1] = __floats2half2_rn(v.z, v.w);
}

__global__ void cvt_fp16_pad_kernel(const float4* __restrict__ src,
                                    __half2* __restrict__ dst,
                                    size_t n4v, size_t n4t)
{
    size_t i = (size_t)blockIdx.x * blockDim.x + threadIdx.x;
    if (i >= n4t) return;
    float4 v = (i < n4v) ? src[i] : make_float4(0.f, 0.f, 0.f, 0.f);
    dst[2*i]   = __floats2half2_rn(v.x, v.y);
    dst[2*i+1] = __floats2half2_rn(v.z, v.w);
}

// ---------------- causal depthwise conv (K=4) + SiLU -> fp16 ---------------
__global__ __launch_bounds__(256) void conv_silu_kernel(
    const __half* __restrict__ proj, const float* __restrict__ cw,
    __half* __restrict__ xbc)
{
    const int ch = blockIdx.x * 256 + threadIdx.x;
    const int b  = blockIdx.z;
    const int t0 = blockIdx.y * 128;
    const __half* col = proj + (size_t)b * Ll * PROJ_ + INTER_ + ch;
    const float4 w = *(const float4*)&cw[ch * 4];
    float xm3 = 0.f, xm2 = 0.f, xm1 = 0.f;
    if (t0 > 0) {
        xm3 = __half2float(col[(size_t)(t0 - 3) * PROJ_]);
        xm2 = __half2float(col[(size_t)(t0 - 2) * PROJ_]);
        xm1 = __half2float(col[(size_t)(t0 - 1) * PROJ_]);
    }
    __half* dst = xbc + ((size_t)(b * Ll + t0)) * CONVD_ + ch;
    const __half* srcp = col + (size_t)t0 * PROJ_;
#pragma unroll 4
    for (int k = 0; k < 128; k++) {
        float xc = __half2float(srcp[(size_t)k * PROJ_]);
        float acc = w.x * xm3 + w.y * xm2 + w.z * xm1 + w.w * xc;
        float sg = __fdividef(1.f, 1.f + __expf(-acc));
        dst[(size_t)k * CONVD_] = __float2half_rn(acc * sg);
        xm3 = xm2; xm2 = xm1; xm1 = xc;
    }
}

// ---------------- P = C * B^T (fp32 acc, fp16 in/out) ----------------------
__device__ __constant__ int c_PI[10] = {0,1,1,2,2,2,3,3,3,3};
__device__ __constant__ int c_PJ[10] = {0,0,1,0,1,2,0,1,2,3};

__global__ __launch_bounds__(256, 3) void pmat_kernel(
    const __half* __restrict__ xbc, __half* __restrict__ P)
{
    const int p = blockIdx.x, c = blockIdx.y, b = blockIdx.z;
    const int i = c_PI[p], j = c_PJ[p];
    const int tid = threadIdx.x;
    extern __shared__ float sm[];
    float* CsT = sm;              // [128][68]
    float* BsT = CsT + 128 * 68;  // [128][68]
    const size_t rowbase = (size_t)(b * Ll + c * CS_);

    for (int idx = tid; idx < 64 * 128; idx += 256) {
        int tl = idx >> 7, n = idx & 127;
        CsT[n * 68 + tl] =
            __half2float(xbc[(rowbase + i * 64 + tl) * CONVD_ + (INTER_ + ST_) + n]);
        BsT[n * 68 + tl] =
            __half2float(xbc[(rowbase + j * 64 + tl) * CONVD_ + INTER_ + n]);
    }
    __syncthreads();

    const int tx = tid & 15, ty = tid >> 4;
    const int t0 = ty * 4, s0 = tx * 4;
    float pf[4][4];
#pragma unroll
    for (int r = 0; r < 4; r++)
#pragma unroll
        for (int q = 0; q < 4; q++) pf[r][q] = 0.f;
    for (int n = 0; n < 128; n++) {
        float4 c4 = *(const float4*)&CsT[n * 68 + t0];
        float4 b4 = *(const float4*)&BsT[n * 68 + s0];
        float cr[4] = {c4.x, c4.y, c4.z, c4.w};
        float br[4] = {b4.x, b4.y, b4.z, b4.w};
#pragma unroll
        for (int r = 0; r < 4; r++)
#pragma unroll
            for (int q = 0; q < 4; q++)
                pf[r][q] = fmaf(cr[r], br[q], pf[r][q]);
    }
    __half* dst = P + ((size_t)(b * NC_ + c) * CS_) * CS_;
#pragma unroll
    for (int r = 0; r < 4; r++) {
        __half2 o0 = __floats2half2_rn(pf[r][0], pf[r][1]);
        __half2 o1 = __floats2half2_rn(pf[r][2], pf[r][3]);
        __half2* dp = (__half2*)&dst[(size_t)(i * 64 + t0 + r) * CS_ + j * 64 + s0];
        dp[0] = o0; dp[1] = o1;
    }
}

// ---------------- intra-chunk scan: fp16 mma, x tiles cached ----------------
__global__ __launch_bounds__(256) void scan_intra_kernel(
    const float* __restrict__ dtraw, const __half* __restrict__ xbc,
    const __half* __restrict__ gP,
    const float* __restrict__ dt_bias, const float* __restrict__ A_log,
    __half* __restrict__ ydiag, float* __restrict__ states,
    float* __restrict__ cumg, float* __restrict__ alast)
{
    const int h = blockIdx.x, c = blockIdx.y, b = blockIdx.z;
    const int tid = threadIdx.x;
    extern __shared__ __align__(128) char smem[];
    char* PwS  = smem;
    char* xAll = smem + 8192;
    char* BwS  = smem + 40960;
    float* dsh   = (float*)(smem + 57344);
    float* cum   = dsh + 256;
    float* wlast = cum + 256;
    float* Esh   = wlast + 256;
    uint32_t sb = cvta_smem(smem);

    {
        float Ah = -__expf(A_log[h]);
        float v = dtraw[(size_t)(b * Ll + c * CS_ + tid) * NH_ + h] + dt_bias[h];
        float dtv = (v > 20.f) ? v : log1pf(__expf(v));
        dsh[tid] = dtv;
        cum[tid] = Ah * dtv;
    }
    __syncthreads();
    for (int off = 1; off < 256; off <<= 1) {
        float add = (tid >= off) ? cum[tid - off] : 0.f;
        __syncthreads();
        cum[tid] += add;
        __syncthreads();
    }
    cumg[(size_t)(b * NH_ + h) * Ll + c * CS_ + tid] = cum[tid];
    if (tid == 255) alast[(b * NH_ + h) * NC_ + c] = cum[255];
    wlast[tid] = __expf(cum[255] - cum[tid]);

    const size_t rowbase = (size_t)(b * Ll + c * CS_);
    const int sfix = tid & 63, rfix = tid >> 6;

#pragma unroll
    for (int jt = 0; jt < 4; jt++) {
        char* xt = xAll + jt * 8192;
        const int p = sfix;
#pragma unroll
        for (int k = 0; k < 16; k++) {
            int s = rfix + 4 * k;
            float v = __half2float(
                          xbc[(rowbase + jt * 64 + s) * CONVD_ + h * HD_ + p])
                      * dsh[jt * 64 + s];
            *(__half*)(xt + swz(p, s)) = __float2half_rn(v);
        }
    }

    const int lid = tid & 31, wid = tid >> 5;
    const int tm = (wid & 3) * 16;
    const int pn = (wid >> 2) * 32;
    const int nn = (wid >> 2) * 64;
    const int lr = lid & 15;
    const int lkb = (lid >> 4) * 16;

    uint32_t roff;
    {
        int row = tm + lr;
        roff = (uint32_t)(row * 128) + (uint32_t)(((row & 7) * 16) ^ lkb);
    }
    uint32_t boffX[2], boffB[4];
#pragma unroll
    for (int ni = 0; ni < 2; ni++) {
        int row = pn + ni * 16 + lr;
        boffX[ni] = (uint32_t)(row * 128) + (uint32_t)(((row & 7) * 16) ^ lkb);
    }
#pragma unroll
    for (int ni = 0; ni < 4; ni++) {
        int row = nn + ni * 16 + lr;
        boffB[ni] = (uint32_t)(row * 128) + (uint32_t)(((row & 7) * 16) ^ lkb);
    }

    float stacc[8][4];
#pragma unroll
    for (int nj = 0; nj < 8; nj++)
#pragma unroll
        for (int q = 0; q < 4; q++) stacc[nj][q] = 0.f;

    const __half* Pblk = gP + ((size_t)(b * NC_ + c) * CS_) * CS_;

    for (int i = 0; i < 4; i++) {
        if (tid < 64) Esh[tid] = __expf(cum[i * 64 + tid] - cum[i * 64]);
        float yacc[4][4];
#pragma unroll
        for (int nj = 0; nj < 4; nj++)
#pragma unroll
            for (int q = 0; q < 4; q++) yacc[nj][q] = 0.f;

        for (int j = 0; j <= i; j++) {
            __syncthreads();
            if (j == i) {
                const int n = tid & 127;
#pragma unroll
                for (int k = 0; k < 32; k++) {
                    int s = (tid >> 7) + 2 * k;
                    float v = __half2float(
                                  xbc[(rowbase + i * 64 + s) * CONVD_ + INTER_ + n])
                              * wlast[i * 64 + s];
                    *(__half*)(BwS + swz(n, s)) = __float2half_rn(v);
                }
                // diagonal tile: skip masked rows (skips load + exp)
                const int s = sfix;
#pragma unroll
                for (int k = 0; k < 16; k++) {
                    int tl = rfix + 4 * k;
                    __half pw = __float2half(0.f);
                    if (s <= tl) {
                        float w = __expf(cum[i*64 + tl] - cum[i*64 + s]);
                        pw = __float2half_rn(
                            __half2float(Pblk[(size_t)(i*64 + tl) * CS_ + i*64 + s]) * w);
                    }
                    *(__half*)(PwS + swz(tl, s)) = pw;
                }
            } else {
                const int s = sfix;
                float rs = __expf(cum[i * 64] - cum[j * 64 + s]);
#pragma unroll
                for (int k = 0; k < 16; k++) {
                    int tl = rfix + 4 * k;
                    *(__half*)(PwS + swz(tl, s)) =
                        __float2half_rn(
                            __half2float(Pblk[(size_t)(i*64 + tl) * CS_ + j*64 + s])
                            * Esh[tl] * rs);
                }
            }
            __syncthreads();
            const uint32_t pwb = sb, xjb = sb + 8192u + (uint32_t)j * 8192u;
#pragma unroll
            for (int ks = 0; ks < 4; ks++) {
                uint32_t kx = (uint32_t)(ks * 32);
                uint32_t a[4];
                ldsm4(a, pwb + (roff ^ kx));
#pragma unroll
                for (int ni = 0; ni < 2; ni++) {
                    uint32_t bf[4];
                    ldsm4(bf, xjb + (boffX[ni] ^ kx));
                    mma16816(yacc[2*ni],   a, bf[0], bf[2]);
                    mma16816(yacc[2*ni+1], a, bf[1], bf[3]);
                }
            }
            if (j == i) {
                const uint32_t bwb = sb + 40960u;
                const uint32_t xib = sb + 8192u + (uint32_t)i * 8192u;
#pragma unroll
                for (int ks = 0; ks < 4; ks++) {
                    uint32_t kx = (uint32_t)(ks * 32);
                    uint32_t a[4];
                    ldsm4(a, xib + (roff ^ kx));
#pragma unroll
                    for (int ni = 0; ni < 4; ni++) {
                        uint32_t bf[4];
                        ldsm4(bf, bwb + (boffB[ni] ^ kx));
                        mma16816(stacc[2*ni],   a, bf[0], bf[2]);
                        mma16816(stacc[2*ni+1], a, bf[1], bf[3]);
                    }
                }
            }
        }
        {
            const int er = lid >> 2, ec = (lid & 3) * 2;
#pragma unroll
            for (int nj = 0; nj < 4; nj++) {
                int p = pn + nj * 8 + ec;
                size_t tg = rowbase + i * 64 + tm + er;
                *(__half2*)&ydiag[(tg * NH_ + h) * HD_ + p] =
                    __floats2half2_rn(yacc[nj][0], yacc[nj][1]);
                *(__half2*)&ydiag[((tg + 8) * NH_ + h) * HD_ + p] =
                    __floats2half2_rn(yacc[nj][2], yacc[nj][3]);
            }
        }
    }
    {
        const int er = lid >> 2, ec = (lid & 3) * 2;
        size_t base = ((size_t)((b * NC_ + c) * NH_ + h)) * HD_;
#pragma unroll
        for (int nj = 0; nj < 8; nj++) {
            int p = tm + er, n = nn + nj * 8 + ec;
            *(float2*)&states[(base + p) * ST_ + n] =
                make_float2(stacc[nj][0], stacc[nj][1]);
            *(float2*)&states[(base + p + 8) * ST_ + n] =
                make_float2(stacc[nj][2], stacc[nj][3]);
        }
    }
}

// ---------------- inter-chunk recurrence (prev -> fp16) --------------------
__global__ void interchunk_kernel(const float* __restrict__ states,
                                  const float* __restrict__ alast,
                                  __half* __restrict__ prev)
{
    int bh = blockIdx.x;
    int b = bh >> 6, h = bh & 63;
    float dec[NC_];
#pragma unroll
    for (int c = 0; c < NC_; c++)
        dec[c] = __expf(alast[(b * NH_ + h) * NC_ + c]);
    for (int e = threadIdx.x; e < HD_ * ST_; e += 256) {
        float run = 0.f;
#pragma unroll
        for (int c = 0; c < NC_; c++) {
            size_t idx = ((size_t)((b * NC_ + c) * NH_ + h)) * (HD_ * ST_) + e;
            prev[idx] = __float2half_rn(run);
            run = fmaf(run, dec[c] - 1.f, run);
            run = run + states[idx];
        }
    }
}

// ---------------- Y_off via fp16 mma + D-skip (fp16 y RMW) ------------------
__global__ __launch_bounds__(256) void scan_off_kernel(
    const __half* __restrict__ xbc, const float* __restrict__ cumg,
    const __half* __restrict__ prev, const float* __restrict__ Dv,
    __half* __restrict__ y)
{
    const int h = blockIdx.x, c = blockIdx.y, b = blockIdx.z;
    const int tid = threadIdx.x;
    extern __shared__ __align__(128) char smem[];
    char* CsS   = smem;
    char* prevS = smem + 16384;
    float* esh  = (float*)(smem + 32768);
    uint32_t sb = cvta_smem(smem);

    size_t sbase = ((size_t)((b * NC_ + c) * NH_ + h)) * (HD_ * ST_);
    for (int idx = tid; idx < 64 * 128; idx += 256) {
        int p = idx >> 7, n = idx & 127;
        *(__half*)(prevS + (n >> 6) * 8192 + swz(p, n & 63)) = prev[sbase + idx];
    }
    esh[tid] = __expf(cumg[(size_t)(b * NH_ + h) * Ll + c * CS_ + tid]);
    const float Dh = Dv[h];
    const size_t rowbase = (size_t)(b * Ll + c * CS_);

    const int lid = tid & 31, wid = tid >> 5;
    const int tm = (wid & 3) * 16, pn = (wid >> 2) * 32;
    const int lr = lid & 15;
    const int lkb = (lid >> 4) * 16;
    uint32_t aoffC, boffP[2];
    {
        int row = tm + lr;
        aoffC = (uint32_t)(row * 128) + (uint32_t)(((row & 7) * 16) ^ lkb);
    }
#pragma unroll
    for (int ni = 0; ni < 2; ni++) {
        int row = pn + ni * 16 + lr;
        boffP[ni] = (uint32_t)(row * 128) + (uint32_t)(((row & 7) * 16) ^ lkb);
    }

    for (int ti = 0; ti < 4; ti++) {
        __syncthreads();
        for (int idx = tid; idx < 64 * 128; idx += 256) {
            int t = idx >> 7, n = idx & 127;
            *(__half*)(CsS + (n >> 6) * 8192 + swz(t, n & 63)) =
                xbc[(rowbase + ti * 64 + t) * CONVD_ + (INTER_ + ST_) + n];
        }
        __syncthreads();
        float acc[4][4];
#pragma unroll
        for (int nj = 0; nj < 4; nj++)
#pragma unroll
            for (int q = 0; q < 4; q++) acc[nj][q] = 0.f;
#pragma unroll
        for (int kt = 0; kt < 2; kt++) {
            uint32_t cb = sb + (uint32_t)kt * 8192u;
            uint32_t pb = sb + 16384u + (uint32_t)kt * 8192u;
#pragma unroll
            for (int ks = 0; ks < 4; ks++) {
                uint32_t kx = (uint32_t)(ks * 32);
                uint32_t a[4];
                ldsm4(a, cb + (aoffC ^ kx));
#pragma unroll
                for (int ni = 0; ni < 2; ni++) {
                    uint32_t bf[4];
                    ldsm4(bf, pb + (boffP[ni] ^ kx));
                    mma16816(acc[2*ni],   a, bf[0], bf[2]);
                    mma16816(acc[2*ni+1], a, bf[1], bf[3]);
                }
            }
        }
        const int er = lid >> 2, ec = (lid & 3) * 2;
#pragma unroll
        for (int nj = 0; nj < 4; nj++) {
            int p = pn + nj * 8 + ec;
            int t0g = ti * 64 + tm + er;
            size_t tg = rowbase + t0g;
            float e0 = esh[t0g], e1 = esh[t0g + 8];
            __half2* yp0 = (__half2*)&y[(tg * NH_ + h) * HD_ + p];
            __half2* yp1 = (__half2*)&y[((tg + 8) * NH_ + h) * HD_ + p];
            float2 yv0 = __half22float2(*yp0), yv1 = __half22float2(*yp1);
            float2 xv0 = __half22float2(
                *(const __half2*)&xbc[tg * CONVD_ + h * HD_ + p]);
            float2 xv1 = __half22float2(
                *(const __half2*)&xbc[(tg + 8) * CONVD_ + h * HD_ + p]);
            yv0.x += acc[nj][0] * e0 + Dh * xv0.x;
            yv0.y += acc[nj][1] * e0 + Dh * xv0.y;
            yv1.x += acc[nj][2] * e1 + Dh * xv1.x;
            yv1.y += acc[nj][3] * e1 + Dh * xv1.y;
            *yp0 = __floats2half2_rn(yv0.x, yv0.y);
            *yp1 = __floats2half2_rn(yv1.x, yv1.y);
        }
    }
}

// ---------------- gated RMSNorm -> fp16 A for GEMM2 ------------------------
__global__ __launch_bounds__(256) void gated_norm_kernel(
    const __half* __restrict__ proj, const __half* __restrict__ y,
    const float* __restrict__ nw, __half* __restrict__ gf)
{
    int row = blockIdx.x;
    int tid = threadIdx.x;
    float gv[16];
    float ss = 0.f;
    const __half* yr = y + (size_t)row * INTER_;
    const __half* gr = proj + (size_t)row * PROJ_;
#pragma unroll
    for (int k = 0; k < 16; k++) {
        int idx = tid + k * 256;
        float gt = __half2float(gr[idx]);
        float s = __fdividef(1.f, 1.f + __expf(-gt));
        float v = __half2float(yr[idx]) * gt * s;
        gv[k] = v;
        ss = fmaf(v, v, ss);
    }
    __shared__ float red[256];
    red[tid] = ss;
    __syncthreads();
    for (int off = 128; off > 0; off >>= 1) {
        if (tid < off) red[tid] += red[tid + off];
        __syncthreads();
    }
    float scale = rsqrtf(red[0] / (float)INTER_ + 1e-5f);
#pragma unroll
    for (int k = 0; k < 16; k++) {
        int idx = tid + k * 256;
        gf[(size_t)row * INTER_ + idx] = __float2half_rn(gv[k] * scale * nw[idx]);
    }
}

// ---------------- launch ----------------------------------------------------
extern "C" void kernel_launch(void* const* d_in, const int* in_sizes, int n_in,
                              void* d_out, int out_size)
{
    const float* hidden  = (const float*)d_in[0];
    const float* in_w    = (const float*)d_in[1];
    const float* in_b    = (const float*)d_in[2];
    const float* conv_w  = (const float*)d_in[3];
    const float* dt_bias = (const float*)d_in[4];
    const float* A_log   = (const float*)d_in[5];
    const float* Dv      = (const float*)d_in[6];
    const float* norm_w  = (const float*)d_in[7];
    const float* out_w   = (const float*)d_in[8];
    const float* out_b   = (const float*)d_in[9];
    float* out = (float*)d_out;

    float *dtraw, *states, *cum, *al;
    __half *proj, *xbc, *y, *prev, *Pm, *Af, *W1, *W2;
    cudaGetSymbolAddress((void**)&proj,   g_proj);
    cudaGetSymbolAddress((void**)&dtraw,  g_dtraw);
    cudaGetSymbolAddress((void**)&xbc,    g_xbc);
    cudaGetSymbolAddress((void**)&y,      g_y);
    cudaGetSymbolAddress((void**)&states, g_states);
    cudaGetSymbolAddress((void**)&prev,   g_prev);
    cudaGetSymbolAddress((void**)&cum,    g_cum);
    cudaGetSymbolAddress((void**)&al,     g_alast);
    cudaGetSymbolAddress((void**)&Pm,     g_P);
    cudaGetSymbolAddress((void**)&Af,     g_Af);
    cudaGetSymbolAddress((void**)&W1,     g_W1);
    cudaGetSymbolAddress((void**)&W2,     g_W2);

    const int SMEM_PMAT  = (128 * 68 * 2) * 4;
    const int SMEM_INTRA = 57344 + (256 * 3 + 64) * 4;
    const int SMEM_OFF   = 32768 + 256 * 4;
    cudaFuncSetAttribute(pmat_kernel,
                         cudaFuncAttributeMaxDynamicSharedMemorySize, SMEM_PMAT);
    cudaFuncSetAttribute(scan_intra_kernel,
                         cudaFuncAttributeMaxDynamicSharedMemorySize, SMEM_INTRA);
    cudaFuncSetAttribute(scan_off_kernel,
                         cudaFuncAttributeMaxDynamicSharedMemorySize, SMEM_OFF);
    cudaFuncSetAttribute(tc_gemm_bias<__half>,
                         cudaFuncAttributeMaxDynamicSharedMemorySize, GSMEM);
    cudaFuncSetAttribute(tc_gemm_bias<float>,
                         cudaFuncAttributeMaxDynamicSharedMemorySize, GSMEM);

    // 0. fp16 conversions
    {
        size_t n4 = (size_t)MT * HIDDEN_ / 4;
        cvt_fp16_kernel<<<(int)((n4 + 255) / 256), 256>>>(
            (const float4*)hidden, (__half2*)Af, n4);
        size_t n4v = (size_t)PROJ_ * HIDDEN_ / 4, n4t = (size_t)NP1 * HIDDEN_ / 4;
        cvt_fp16_pad_kernel<<<(int)((n4t + 255) / 256), 256>>>(
            (const float4*)in_w, (__half2*)W1, n4v, n4t);
        n4 = (size_t)HIDDEN_ * INTER_ / 4;
        cvt_fp16_kernel<<<(int)((n4 + 255) / 256), 256>>>(
            (const float4*)out_w, (__half2*)W2, n4);
    }

    // 1. in_proj GEMM + bias -> fp16 proj + fp32 dt side-channel
    tc_gemm_bias<__half><<<dim3(NP1 / 128, MT / 128), 256, GSMEM>>>(
        Af, W1, in_b, proj, dtraw, PROJ_, HIDDEN_);

    // 2. causal depthwise conv + SiLU -> fp16 xbc
    conv_silu_kernel<<<dim3(CONVD_ / 256, Ll / 128, Bb), 256>>>(proj, conv_w, xbc);

    // 2b. shared P = C * B^T per (b, chunk) -> fp16
    pmat_kernel<<<dim3(10, NC_, Bb), 256, SMEM_PMAT>>>(xbc, Pm);

    // 3. intra-chunk scan (fp16 mma, fp16 P)
    scan_intra_kernel<<<dim3(NH_, NC_, Bb), 256, SMEM_INTRA>>>(
        dtraw, xbc, Pm, dt_bias, A_log, y, states, cum, al);

    // 4. inter-chunk recurrence -> fp16 prev
    interchunk_kernel<<<Bb * NH_, 256>>>(states, al, prev);

    // 5. inter-chunk output contribution + D skip
    scan_off_kernel<<<dim3(NH_, NC_, Bb), 256, SMEM_OFF>>>(xbc, cum, prev, Dv, y);

    // 6. gated RMSNorm -> fp16 A for GEMM2
    gated_norm_kernel<<<MT, 256>>>(proj, y, norm_w, Af);

    // 7. out_proj GEMM + bias -> fp32 out
    tc_gemm_bias<float><<<dim3(HIDDEN_ / 128, MT / 128), 256, GSMEM>>>(
        Af, W2, out_b, out, nullptr, HIDDEN_, INTER_);
}

// round 16
// speedup vs baseline: 1.2121x; 1.1832x over previous
#include <cuda_runtime.h>
#include <cuda_bf16.h>
#include <cuda_fp16.h>
#include <math.h>
#include <cstdint>

#define Bb      2
#define Ll      2048
#define HIDDEN_ 2048
#define PROJ_   8512
#define INTER_  4096
#define CONVD_  4352
#define NH_     64
#define HD_     64
#define ST_     128
#define NC_     8
#define CS_     256
#define MT      (Bb*Ll)      // 4096
#define NP1     8576
#define DTOFF   (INTER_ + CONVD_)   // 8448, tile-aligned

// ---------------- static scratch ----------------
__device__ __half g_proj  [(size_t)MT*PROJ_];
__device__ float  g_dtraw [(size_t)MT*NH_];
__device__ __half g_xbc   [(size_t)MT*CONVD_];
__device__ __half g_y     [(size_t)MT*INTER_];
__device__ float  g_states[(size_t)Bb*NC_*NH_*HD_*ST_];
__device__ __half g_prev  [(size_t)Bb*NC_*NH_*HD_*ST_];
__device__ float  g_cum   [(size_t)Bb*NH_*Ll];
__device__ float  g_alast [(size_t)Bb*NH_*NC_];
__device__ __half g_P     [(size_t)Bb*NC_*CS_*CS_];
__device__ __half g_Af [(size_t)MT*INTER_];
__device__ __half g_W1 [(size_t)NP1*HIDDEN_];
__device__ __half g_W2 [(size_t)HIDDEN_*INTER_];

// ======================= warp-MMA helpers ====================
__device__ __forceinline__ uint32_t cvta_smem(const void* p) {
    uint32_t a;
    asm("{ .reg .u64 t; cvta.to.shared.u64 t, %1; cvt.u32.u64 %0, t; }"
        : "=r"(a) : "l"(p));
    return a;
}

__device__ __forceinline__ void ldsm4(uint32_t* r, uint32_t addr) {
    asm volatile("ldmatrix.sync.aligned.m8n8.x4.shared.b16 {%0,%1,%2,%3}, [%4];"
                 : "=r"(r[0]), "=r"(r[1]), "=r"(r[2]), "=r"(r[3]) : "r"(addr));
}

__device__ __forceinline__ void mma16816(float* c, const uint32_t* a,
                                         uint32_t b0, uint32_t b1) {
    asm volatile(
        "mma.sync.aligned.m16n8k16.row.col.f32.f16.f16.f32 "
        "{%0,%1,%2,%3}, {%4,%5,%6,%7}, {%8,%9}, {%0,%1,%2,%3};"
        : "+f"(c[0]), "+f"(c[1]), "+f"(c[2]), "+f"(c[3])
        : "r"(a[0]), "r"(a[1]), "r"(a[2]), "r"(a[3]), "r"(b0), "r"(b1));
}

__device__ __forceinline__ uint32_t swz(int row, int col) {
    return (uint32_t)(row * 128) + (uint32_t)(((col * 2) ^ ((row & 7) << 4)));
}

#define CPASYNC16(sa, ga) \
    asm volatile("cp.async.cg.shared.global [%0], [%1], 16;" :: "r"(sa), "l"(ga) : "memory")

// GEMM tiling: BM=128, BN=128, BK=64, 256 threads, 2 CTAs/SM, 3 stages
#define ATILEB 16384u
#define STAGEB 32768u
#define NSTG   3
#define GSMEM  (1024 + NSTG*32768)

// =========================================================================
// single-pass fp16 tensor-core GEMM: C = A*W^T + bias (templated output)
// =========================================================================
template<typename TOut>
__global__ __launch_bounds__(256, 2)
void tc_gemm_bias(
    const __half* __restrict__ A, const __half* __restrict__ W,
    const float* __restrict__ bias, TOut* __restrict__ C,
    float* __restrict__ dtsave, int N, int K)
{
    extern __shared__ __align__(128) char smem[];
    const int tid = threadIdx.x;
    const int lid = tid & 31, wid = tid >> 5;
    uint32_t sb = cvta_smem(smem);
    uint32_t tb = (sb + 1023u) & ~1023u;

    const size_t arow = (size_t)blockIdx.y * 128;
    const size_t brow = (size_t)blockIdx.x * 128;
    const int NCH = K >> 6;

    const int seg = tid & 7, r0 = tid >> 3;
    uint32_t so[4];
#pragma unroll
    for (int k = 0; k < 4; k++) {
        uint32_t off = (uint32_t)((r0 + 32 * k) * 128 + seg * 16);
        so[k] = off ^ ((off >> 3) & 0x70);
    }
    const __half* pA = A + (arow + r0) * (size_t)K + (seg << 3);
    const __half* pW = W + (brow + r0) * (size_t)K + (seg << 3);
    const size_t off32 = (size_t)32 * K;

#define LOAD_STAGE(s)                                                     \
    do {                                                                  \
        uint32_t stb_ = tb + (uint32_t)(s) * STAGEB;                      \
        CPASYNC16(stb_ + so[0], pA);                                      \
        CPASYNC16(stb_ + so[1], pA + off32);                              \
        CPASYNC16(stb_ + so[2], pA + 2 * off32);                          \
        CPASYNC16(stb_ + so[3], pA + 3 * off32);                          \
        CPASYNC16(stb_ + ATILEB + so[0], pW);                             \
        CPASYNC16(stb_ + ATILEB + so[1], pW + off32);                     \
        CPASYNC16(stb_ + ATILEB + so[2], pW + 2 * off32);                 \
        CPASYNC16(stb_ + ATILEB + so[3], pW + 3 * off32);                 \
        asm volatile("cp.async.commit_group;" ::: "memory");              \
        pA += 64; pW += 64;                                               \
    } while (0)

    const int wm = wid & 3, wn = wid >> 2;
    const int m0 = wm * 32, n0 = wn * 64;
    const int lr  = lid & 15;
    const int lkb = (lid >> 4) * 16;

    float acc[2][8][4];
#pragma unroll
    for (int mi = 0; mi < 2; mi++)
#pragma unroll
        for (int nj = 0; nj < 8; nj++)
#pragma unroll
            for (int q = 0; q < 4; q++) acc[mi][nj][q] = 0.f;

    uint32_t aoff[2], boff[4];
#pragma unroll
    for (int mi = 0; mi < 2; mi++) {
        int row = m0 + mi * 16 + lr;
        aoff[mi] = (uint32_t)(row * 128) + (uint32_t)(((row & 7) * 16) ^ lkb);
    }
#pragma unroll
    for (int ni = 0; ni < 4; ni++) {
        int row = n0 + ni * 16 + lr;
        boff[ni] = (uint32_t)(row * 128) + (uint32_t)(((row & 7) * 16) ^ lkb);
    }

    LOAD_STAGE(0);
    LOAD_STAGE(1);

    for (int c = 0; c < NCH; c++) {
        if (c + 1 < NCH) asm volatile("cp.async.wait_group 1;" ::: "memory");
        else             asm volatile("cp.async.wait_group 0;" ::: "memory");
        __syncthreads();
        if (c + 2 < NCH) LOAD_STAGE((c + 2) % NSTG);

        uint32_t stb = tb + (uint32_t)(c % NSTG) * STAGEB;
#pragma unroll
        for (int kk = 0; kk < 4; kk++) {
            uint32_t kx = (uint32_t)(kk * 32);
            uint32_t a_f[2][4];
#pragma unroll
            for (int mi = 0; mi < 2; mi++)
                ldsm4(a_f[mi], stb + (aoff[mi] ^ kx));
            uint32_t w_f[4][4];
#pragma unroll
            for (int ni = 0; ni < 4; ni++)
                ldsm4(w_f[ni], stb + ATILEB + (boff[ni] ^ kx));
#pragma unroll
            for (int mi = 0; mi < 2; mi++)
#pragma unroll
                for (int ni = 0; ni < 4; ni++) {
                    mma16816(acc[mi][2*ni],   a_f[mi], w_f[ni][0], w_f[ni][2]);
                    mma16816(acc[mi][2*ni+1], a_f[mi], w_f[ni][1], w_f[ni][3]);
                }
        }
    }

    const int er = lid >> 2;
    const int ec = (lid & 3) * 2;
#pragma unroll
    for (int mi = 0; mi < 2; mi++) {
        int grow0 = (int)arow + m0 + mi * 16 + er;
#pragma unroll
        for (int nj = 0; nj < 8; nj++) {
            int gcol = (int)brow + n0 + nj * 8 + ec;
            if (gcol + 1 < N) {
                float b0 = __ldg(&bias[gcol]), b1 = __ldg(&bias[gcol + 1]);
                float v00 = acc[mi][nj][0] + b0, v01 = acc[mi][nj][1] + b1;
                float v10 = acc[mi][nj][2] + b0, v11 = acc[mi][nj][3] + b1;
                if (sizeof(TOut) == 2) {
                    *(__half2*)&C[(size_t)grow0 * N + gcol] =
                        __floats2half2_rn(v00, v01);
                    *(__half2*)&C[(size_t)(grow0 + 8) * N + gcol] =
                        __floats2half2_rn(v10, v11);
                } else {
                    *(float2*)&C[(size_t)grow0 * N + gcol] = make_float2(v00, v01);
                    *(float2*)&C[(size_t)(grow0 + 8) * N + gcol] = make_float2(v10, v11);
                }
                if (dtsave && gcol >= DTOFF) {
                    int dcol = gcol - DTOFF;
                    *(float2*)&dtsave[(size_t)grow0 * NH_ + dcol] =
                        make_float2(v00, v01);
                    *(float2*)&dtsave[(size_t)(grow0 + 8) * NH_ + dcol] =
                        make_float2(v10, v11);
                }
            } else if (gcol < N) {
                float b0 = __ldg(&bias[gcol]);
                float v0 = acc[mi][nj][0] + b0, v1 = acc[mi][nj][2] + b0;
                if (sizeof(TOut) == 2) {
                    C[(size_t)grow0 * N + gcol] = (TOut)__float2half_rn(v0);
                    C[(size_t)(grow0 + 8) * N + gcol] = (TOut)__float2half_rn(v1);
                } else {
                    C[(size_t)grow0 * N + gcol] = (TOut)v0;
                    C[(size_t)(grow0 + 8) * N + gcol] = (TOut)v1;
                }
                if (dtsave && gcol >= DTOFF) {
                    int dcol = gcol - DTOFF;
                    dtsave[(size_t)grow0 * NH_ + dcol] = v0;
                    dtsave[(size_t)(grow0 + 8) * NH_ + dcol] = v1;
                }
            }
        }
    }
#undef LOAD_STAGE
}

// ---------------- fp32 -> fp16 conversions ---------------------------------
__global__ void cvt_fp16_kernel(const float4* __restrict__ src,
                                __half2* __restrict__ dst, size_t n4)
{
    size_t i = (size_t)blockIdx.x * blockDim.x + threadIdx.x;
    if (i >= n4) return;
    float4 v = src[i];
    dst[2*i]   = __floats2half2_rn(v.x, v.y);
    dst[2*i+1] = __floats2half2_rn(v.z, v.w);
}

__global__ void cvt_fp16_pad_kernel(const float4* __restrict__ src,
                                    __half2* __restrict__ dst,
                                    size_t n4v, size_t n4t)
{
    size_t i = (size_t)blockIdx.x * blockDim.x + threadIdx.x;
    if (i >= n4t) return;
    float4 v = (i < n4v) ? src[i] : make_float4(0.f, 0.f, 0.f, 0.f);
    dst[2*i]   = __floats2half2_rn(v.x, v.y);
    dst[2*i+1] = __floats2half2_rn(v.z, v.w);
}

// ---------------- causal depthwise conv (K=4) + SiLU -> fp16 ---------------
__global__ __launch_bounds__(256) void conv_silu_kernel(
    const __half* __restrict__ proj, const float* __restrict__ cw,
    __half* __restrict__ xbc)
{
    const int ch = blockIdx.x * 256 + threadIdx.x;
    const int b  = blockIdx.z;
    const int t0 = blockIdx.y * 128;
    const __half* col = proj + (size_t)b * Ll * PROJ_ + INTER_ + ch;
    const float4 w = *(const float4*)&cw[ch * 4];
    float xm3 = 0.f, xm2 = 0.f, xm1 = 0.f;
    if (t0 > 0) {
        xm3 = __half2float(col[(size_t)(t0 - 3) * PROJ_]);
        xm2 = __half2float(col[(size_t)(t0 - 2) * PROJ_]);
        xm1 = __half2float(col[(size_t)(t0 - 1) * PROJ_]);
    }
    __half* dst = xbc + ((size_t)(b * Ll + t0)) * CONVD_ + ch;
    const __half* srcp = col + (size_t)t0 * PROJ_;
#pragma unroll 4
    for (int k = 0; k < 128; k++) {
        float xc = __half2float(srcp[(size_t)k * PROJ_]);
        float acc = w.x * xm3 + w.y * xm2 + w.z * xm1 + w.w * xc;
        float sg = __fdividef(1.f, 1.f + __expf(-acc));
        dst[(size_t)k * CONVD_] = __float2half_rn(acc * sg);
        xm3 = xm2; xm2 = xm1; xm1 = xc;
    }
}

// ---------------- P = C * B^T (fp32 acc, fp16 in/out) ----------------------
__device__ __constant__ int c_PI[10] = {0,1,1,2,2,2,3,3,3,3};
__device__ __constant__ int c_PJ[10] = {0,0,1,0,1,2,0,1,2,3};

__global__ __launch_bounds__(256, 3) void pmat_kernel(
    const __half* __restrict__ xbc, __half* __restrict__ P)
{
    const int p = blockIdx.x, c = blockIdx.y, b = blockIdx.z;
    const int i = c_PI[p], j = c_PJ[p];
    const int tid = threadIdx.x;
    extern __shared__ float sm[];
    float* CsT = sm;              // [128][68]
    float* BsT = CsT + 128 * 68;  // [128][68]
    const size_t rowbase = (size_t)(b * Ll + c * CS_);

    for (int idx = tid; idx < 64 * 128; idx += 256) {
        int tl = idx >> 7, n = idx & 127;
        CsT[n * 68 + tl] =
            __half2float(xbc[(rowbase + i * 64 + tl) * CONVD_ + (INTER_ + ST_) + n]);
        BsT[n * 68 + tl] =
            __half2float(xbc[(rowbase + j * 64 + tl) * CONVD_ + INTER_ + n]);
    }
    __syncthreads();

    const int tx = tid & 15, ty = tid >> 4;
    const int t0 = ty * 4, s0 = tx * 4;
    float pf[4][4];
#pragma unroll
    for (int r = 0; r < 4; r++)
#pragma unroll
        for (int q = 0; q < 4; q++) pf[r][q] = 0.f;
    for (int n = 0; n < 128; n++) {
        float4 c4 = *(const float4*)&CsT[n * 68 + t0];
        float4 b4 = *(const float4*)&BsT[n * 68 + s0];
        float cr[4] = {c4.x, c4.y, c4.z, c4.w};
        float br[4] = {b4.x, b4.y, b4.z, b4.w};
#pragma unroll
        for (int r = 0; r < 4; r++)
#pragma unroll
            for (int q = 0; q < 4; q++)
                pf[r][q] = fmaf(cr[r], br[q], pf[r][q]);
    }
    __half* dst = P + ((size_t)(b * NC_ + c) * CS_) * CS_;
#pragma unroll
    for (int r = 0; r < 4; r++) {
        __half2 o0 = __floats2half2_rn(pf[r][0], pf[r][1]);
        __half2 o1 = __floats2half2_rn(pf[r][2], pf[r][3]);
        __half2* dp = (__half2*)&dst[(size_t)(i * 64 + t0 + r) * CS_ + j * 64 + s0];
        dp[0] = o0; dp[1] = o1;
    }
}

// ---------------- intra-chunk scan: flat 10-step loop, double-buffered PwS --
// smem: PwS0 8K | PwS1 8K | xAll 32K | BwS 16K | dsh/cum/wlast/EshA/wsum
__global__ __launch_bounds__(256) void scan_intra_kernel(
    const float* __restrict__ dtraw, const __half* __restrict__ xbc,
    const __half* __restrict__ gP,
    const float* __restrict__ dt_bias, const float* __restrict__ A_log,
    __half* __restrict__ ydiag, float* __restrict__ states,
    float* __restrict__ cumg, float* __restrict__ alast)
{
    const int h = blockIdx.x, c = blockIdx.y, b = blockIdx.z;
    const int tid = threadIdx.x;
    extern __shared__ __align__(128) char smem[];
    char* xAll = smem + 16384;         // 4 tiles of 8KB
    char* BwS  = smem + 49152;         // 16KB
    float* dsh   = (float*)(smem + 65536);
    float* cum   = dsh + 256;
    float* wlast = cum + 256;
    float* EshA  = wlast + 256;        // [256]
    float* wsum  = EshA + 256;         // [8]
    uint32_t sb = cvta_smem(smem);

    const int lid = tid & 31, wid = tid >> 5;

    // ---- dt, A*dt, warp-shuffle cumsum ----
    {
        float Ah = -__expf(A_log[h]);
        float vr = dtraw[(size_t)(b * Ll + c * CS_ + tid) * NH_ + h] + dt_bias[h];
        float dtv = (vr > 20.f) ? vr : log1pf(__expf(vr));
        dsh[tid] = dtv;
        float v = Ah * dtv;
#pragma unroll
        for (int o = 1; o < 32; o <<= 1) {
            float n = __shfl_up_sync(0xffffffffu, v, o);
            if (lid >= o) v += n;
        }
        if (lid == 31) wsum[wid] = v;
        __syncthreads();
        if (wid == 0 && lid < 8) {
            float w = wsum[lid];
#pragma unroll
            for (int o = 1; o < 8; o <<= 1) {
                float n = __shfl_up_sync(0xffu, w, o);
                if (lid >= o) w += n;
            }
            wsum[lid] = w;
        }
        __syncthreads();
        float tot = v + ((wid > 0) ? wsum[wid - 1] : 0.f);
        float c255 = wsum[7];
        cum[tid] = tot;
        wlast[tid] = __expf(c255 - tot);
        cumg[(size_t)(b * NH_ + h) * Ll + c * CS_ + tid] = tot;
        if (tid == 255) alast[(b * NH_ + h) * NC_ + c] = tot;
    }
    __syncthreads();
    EshA[tid] = __expf(cum[tid] - cum[tid & ~63]);

    const size_t rowbase = (size_t)(b * Ll + c * CS_);
    const int sfix = tid & 63, rfix = tid >> 6;
    const __half* Pblk = gP + ((size_t)(b * NC_ + c) * CS_) * CS_;

    // ---- fill all 4 x tiles ----
#pragma unroll
    for (int jt = 0; jt < 4; jt++) {
        char* xt = xAll + jt * 8192;
        const int p = sfix;
#pragma unroll
        for (int k = 0; k < 16; k++) {
            int s = rfix + 4 * k;
            float v = __half2float(
                          xbc[(rowbase + jt * 64 + s) * CONVD_ + h * HD_ + p])
                      * dsh[jt * 64 + s];
            *(__half*)(xt + swz(p, s)) = __float2half_rn(v);
        }
    }
    // ---- prologue: BwS for i=0 and PwS buf0 for step (0,0) ----
    {
        const int n = tid & 127;
#pragma unroll
        for (int k = 0; k < 32; k++) {
            int s = (tid >> 7) + 2 * k;
            float v = __half2float(xbc[(rowbase + s) * CONVD_ + INTER_ + n])
                      * wlast[s];
            *(__half*)(BwS + swz(n, s)) = __float2half_rn(v);
        }
        const int s = sfix;
#pragma unroll
        for (int k = 0; k < 16; k++) {
            int tl = rfix + 4 * k;
            __half pw = __float2half(0.f);
            if (s <= tl) {
                float w = __expf(cum[tl] - cum[s]);
                pw = __float2half_rn(__half2float(Pblk[(size_t)tl * CS_ + s]) * w);
            }
            *(__half*)(smem + swz(tl, s)) = pw;   // PwS0
        }
    }

    // ---- mma setup ----
    const int tm = (wid & 3) * 16;
    const int pn = (wid >> 2) * 32;
    const int nn = (wid >> 2) * 64;
    const int lr = lid & 15;
    const int lkb = (lid >> 4) * 16;
    uint32_t roff;
    {
        int row = tm + lr;
        roff = (uint32_t)(row * 128) + (uint32_t)(((row & 7) * 16) ^ lkb);
    }
    uint32_t boffX[2], boffB[4];
#pragma unroll
    for (int ni = 0; ni < 2; ni++) {
        int row = pn + ni * 16 + lr;
        boffX[ni] = (uint32_t)(row * 128) + (uint32_t)(((row & 7) * 16) ^ lkb);
    }
#pragma unroll
    for (int ni = 0; ni < 4; ni++) {
        int row = nn + ni * 16 + lr;
        boffB[ni] = (uint32_t)(row * 128) + (uint32_t)(((row & 7) * 16) ^ lkb);
    }

    float stacc[8][4];
#pragma unroll
    for (int nj = 0; nj < 8; nj++)
#pragma unroll
        for (int q = 0; q < 4; q++) stacc[nj][q] = 0.f;
    float yacc[4][4];

    // ---- flat 10-step loop ----
    for (int s9 = 0; s9 < 10; s9++) {
        const int i = c_PI[s9], j = c_PJ[s9];
        __syncthreads();
        // prefetch fills for step s9+1 (disjoint buffers from this step's mma)
        if (s9 + 1 < 10) {
            const int i2 = c_PI[s9 + 1], j2 = c_PJ[s9 + 1];
            char* Pdst = smem + (((s9 + 1) & 1) ? 8192 : 0);
            if (i2 == j2) {
                const int n = tid & 127;
#pragma unroll
                for (int k = 0; k < 32; k++) {
                    int s = (tid >> 7) + 2 * k;
                    float v = __half2float(
                                  xbc[(rowbase + i2 * 64 + s) * CONVD_ + INTER_ + n])
                              * wlast[i2 * 64 + s];
                    *(__half*)(BwS + swz(n, s)) = __float2half_rn(v);
                }
                const int s = sfix;
#pragma unroll
                for (int k = 0; k < 16; k++) {
                    int tl = rfix + 4 * k;
                    __half pw = __float2half(0.f);
                    if (s <= tl) {
                        float w = __expf(cum[i2*64 + tl] - cum[i2*64 + s]);
                        pw = __float2half_rn(
                            __half2float(Pblk[(size_t)(i2*64 + tl) * CS_ + i2*64 + s]) * w);
                    }
                    *(__half*)(Pdst + swz(tl, s)) = pw;
                }
            } else {
                const int s = sfix;
                float rs = __expf(cum[i2 * 64] - cum[j2 * 64 + s]);
#pragma unroll
                for (int k = 0; k < 16; k++) {
                    int tl = rfix + 4 * k;
                    *(__half*)(Pdst + swz(tl, s)) =
                        __float2half_rn(
                            __half2float(Pblk[(size_t)(i2*64 + tl) * CS_ + j2*64 + s])
                            * EshA[i2*64 + tl] * rs);
                }
            }
        }
        if (j == 0) {
#pragma unroll
            for (int nj = 0; nj < 4; nj++)
#pragma unroll
                for (int q = 0; q < 4; q++) yacc[nj][q] = 0.f;
        }
        // Y mma: PwS[s9&1] x xAll[j]
        const uint32_t pwb = sb + (uint32_t)(s9 & 1) * 8192u;
        const uint32_t xjb = sb + 16384u + (uint32_t)j * 8192u;
#pragma unroll
        for (int ks = 0; ks < 4; ks++) {
            uint32_t kx = (uint32_t)(ks * 32);
            uint32_t a[4];
            ldsm4(a, pwb + (roff ^ kx));
#pragma unroll
            for (int ni = 0; ni < 2; ni++) {
                uint32_t bf[4];
                ldsm4(bf, xjb + (boffX[ni] ^ kx));
                mma16816(yacc[2*ni],   a, bf[0], bf[2]);
                mma16816(yacc[2*ni+1], a, bf[1], bf[3]);
            }
        }
        if (i == j) {
            // states mma: xAll[i] x BwS
            const uint32_t bwb = sb + 49152u;
            const uint32_t xib = sb + 16384u + (uint32_t)i * 8192u;
#pragma unroll
            for (int ks = 0; ks < 4; ks++) {
                uint32_t kx = (uint32_t)(ks * 32);
                uint32_t a[4];
                ldsm4(a, xib + (roff ^ kx));
#pragma unroll
                for (int ni = 0; ni < 4; ni++) {
                    uint32_t bf[4];
                    ldsm4(bf, bwb + (boffB[ni] ^ kx));
                    mma16816(stacc[2*ni],   a, bf[0], bf[2]);
                    mma16816(stacc[2*ni+1], a, bf[1], bf[3]);
                }
            }
            // Y epilogue for row-block i (diag is last j of this i)
            const int er = lid >> 2, ec = (lid & 3) * 2;
#pragma unroll
            for (int nj = 0; nj < 4; nj++) {
                int p = pn + nj * 8 + ec;
                size_t tg = rowbase + i * 64 + tm + er;
                *(__half2*)&ydiag[(tg * NH_ + h) * HD_ + p] =
                    __floats2half2_rn(yacc[nj][0], yacc[nj][1]);
                *(__half2*)&ydiag[((tg + 8) * NH_ + h) * HD_ + p] =
                    __floats2half2_rn(yacc[nj][2], yacc[nj][3]);
            }
        }
    }
    // states epilogue
    {
        const int er = lid >> 2, ec = (lid & 3) * 2;
        size_t base = ((size_t)((b * NC_ + c) * NH_ + h)) * HD_;
#pragma unroll
        for (int nj = 0; nj < 8; nj++) {
            int p = tm + er, n = nn + nj * 8 + ec;
            *(float2*)&states[(base + p) * ST_ + n] =
                make_float2(stacc[nj][0], stacc[nj][1]);
            *(float2*)&states[(base + p + 8) * ST_ + n] =
                make_float2(stacc[nj][2], stacc[nj][3]);
        }
    }
}

// ---------------- inter-chunk recurrence (prev -> fp16) --------------------
__global__ void interchunk_kernel(const float* __restrict__ states,
                                  const float* __restrict__ alast,
                                  __half* __restrict__ prev)
{
    int bh = blockIdx.x;
    int b = bh >> 6, h = bh & 63;
    float dec[NC_];
#pragma unroll
    for (int c = 0; c < NC_; c++)
        dec[c] = __expf(alast[(b * NH_ + h) * NC_ + c]);
    for (int e = threadIdx.x; e < HD_ * ST_; e += 256) {
        float run = 0.f;
#pragma unroll
        for (int c = 0; c < NC_; c++) {
            size_t idx = ((size_t)((b * NC_ + c) * NH_ + h)) * (HD_ * ST_) + e;
            prev[idx] = __float2half_rn(run);
            run = fmaf(run, dec[c] - 1.f, run);
            run = run + states[idx];
        }
    }
}

// ---------------- Y_off: double-buffered C tile, fp16 y RMW -----------------
// smem: CsS0 16K | CsS1 16K | prevS 16K | esh 1K
__global__ __launch_bounds__(256) void scan_off_kernel(
    const __half* __restrict__ xbc, const float* __restrict__ cumg,
    const __half* __restrict__ prev, const float* __restrict__ Dv,
    __half* __restrict__ y)
{
    const int h = blockIdx.x, c = blockIdx.y, b = blockIdx.z;
    const int tid = threadIdx.x;
    extern __shared__ __align__(128) char smem[];
    char* prevS = smem + 32768;
    float* esh  = (float*)(smem + 49152);
    uint32_t sb = cvta_smem(smem);

    size_t sbase = ((size_t)((b * NC_ + c) * NH_ + h)) * (HD_ * ST_);
    for (int idx = tid; idx < 64 * 128; idx += 256) {
        int p = idx >> 7, n = idx & 127;
        *(__half*)(prevS + (n >> 6) * 8192 + swz(p, n & 63)) = prev[sbase + idx];
    }
    esh[tid] = __expf(cumg[(size_t)(b * NH_ + h) * Ll + c * CS_ + tid]);
    const float Dh = Dv[h];
    const size_t rowbase = (size_t)(b * Ll + c * CS_);

    // prologue: fill CsS[0] for ti=0
    for (int idx = tid; idx < 64 * 128; idx += 256) {
        int t = idx >> 7, n = idx & 127;
        *(__half*)(smem + (n >> 6) * 8192 + swz(t, n & 63)) =
            xbc[(rowbase + t) * CONVD_ + (INTER_ + ST_) + n];
    }

    const int lid = tid & 31, wid = tid >> 5;
    const int tm = (wid & 3) * 16, pn = (wid >> 2) * 32;
    const int lr = lid & 15;
    const int lkb = (lid >> 4) * 16;
    uint32_t aoffC, boffP[2];
    {
        int row = tm + lr;
        aoffC = (uint32_t)(row * 128) + (uint32_t)(((row & 7) * 16) ^ lkb);
    }
#pragma unroll
    for (int ni = 0; ni < 2; ni++) {
        int row = pn + ni * 16 + lr;
        boffP[ni] = (uint32_t)(row * 128) + (uint32_t)(((row & 7) * 16) ^ lkb);
    }

    for (int ti = 0; ti < 4; ti++) {
        __syncthreads();
        // prefetch CsS for ti+1 (other buffer) while mma runs on this one
        if (ti < 3) {
            char* cd = smem + (((ti + 1) & 1) ? 16384 : 0);
            for (int idx = tid; idx < 64 * 128; idx += 256) {
                int t = idx >> 7, n = idx & 127;
                *(__half*)(cd + (n >> 6) * 8192 + swz(t, n & 63)) =
                    xbc[(rowbase + (ti + 1) * 64 + t) * CONVD_ + (INTER_ + ST_) + n];
            }
        }
        float acc[4][4];
#pragma unroll
        for (int nj = 0; nj < 4; nj++)
#pragma unroll
            for (int q = 0; q < 4; q++) acc[nj][q] = 0.f;
        const uint32_t cbase = sb + (uint32_t)(ti & 1) * 16384u;
#pragma unroll
        for (int kt = 0; kt < 2; kt++) {
            uint32_t cb = cbase + (uint32_t)kt * 8192u;
            uint32_t pb = sb + 32768u + (uint32_t)kt * 8192u;
#pragma unroll
            for (int ks = 0; ks < 4; ks++) {
                uint32_t kx = (uint32_t)(ks * 32);
                uint32_t a[4];
                ldsm4(a, cb + (aoffC ^ kx));
#pragma unroll
                for (int ni = 0; ni < 2; ni++) {
                    uint32_t bf[4];
                    ldsm4(bf, pb + (boffP[ni] ^ kx));
                    mma16816(acc[2*ni],   a, bf[0], bf[2]);
                    mma16816(acc[2*ni+1], a, bf[1], bf[3]);
                }
            }
        }
        const int er = lid >> 2, ec = (lid & 3) * 2;
#pragma unroll
        for (int nj = 0; nj < 4; nj++) {
            int p = pn + nj * 8 + ec;
            int t0g = ti * 64 + tm + er;
            size_t tg = rowbase + t0g;
            float e0 = esh[t0g], e1 = esh[t0g + 8];
            __half2* yp0 = (__half2*)&y[(tg * NH_ + h) * HD_ + p];
            __half2* yp1 = (__half2*)&y[((tg + 8) * NH_ + h) * HD_ + p];
            float2 yv0 = __half22float2(*yp0), yv1 = __half22float2(*yp1);
            float2 xv0 = __half22float2(
                *(const __half2*)&xbc[tg * CONVD_ + h * HD_ + p]);
            float2 xv1 = __half22float2(
                *(const __half2*)&xbc[(tg + 8) * CONVD_ + h * HD_ + p]);
            yv0.x += acc[nj][0] * e0 + Dh * xv0.x;
            yv0.y += acc[nj][1] * e0 + Dh * xv0.y;
            yv1.x += acc[nj][2] * e1 + Dh * xv1.x;
            yv1.y += acc[nj][3] * e1 + Dh * xv1.y;
            *yp0 = __floats2half2_rn(yv0.x, yv0.y);
            *yp1 = __floats2half2_rn(yv1.x, yv1.y);
        }
    }
}

// ---------------- gated RMSNorm -> fp16 A for GEMM2 ------------------------
__global__ __launch_bounds__(256) void gated_norm_kernel(
    const __half* __restrict__ proj, const __half* __restrict__ y,
    const float* __restrict__ nw, __half* __restrict__ gf)
{
    int row = blockIdx.x;
    int tid = threadIdx.x;
    float gv[16];
    float ss = 0.f;
    const __half* yr = y + (size_t)row * INTER_;
    const __half* gr = proj + (size_t)row * PROJ_;
#pragma unroll
    for (int k = 0; k < 16; k++) {
        int idx = tid + k * 256;
        float gt = __half2float(gr[idx]);
        float s = __fdividef(1.f, 1.f + __expf(-gt));
        float v = __half2float(yr[idx]) * gt * s;
        gv[k] = v;
        ss = fmaf(v, v, ss);
    }
    __shared__ float red[256];
    red[tid] = ss;
    __syncthreads();
    for (int off = 128; off > 0; off >>= 1) {
        if (tid < off) red[tid] += red[tid + off];
        __syncthreads();
    }
    float scale = rsqrtf(red[0] / (float)INTER_ + 1e-5f);
#pragma unroll
    for (int k = 0; k < 16; k++) {
        int idx = tid + k * 256;
        gf[(size_t)row * INTER_ + idx] = __float2half_rn(gv[k] * scale * nw[idx]);
    }
}

// ---------------- launch ----------------------------------------------------
extern "C" void kernel_launch(void* const* d_in, const int* in_sizes, int n_in,
                              void* d_out, int out_size)
{
    const float* hidden  = (const float*)d_in[0];
    const float* in_w    = (const float*)d_in[1];
    const float* in_b    = (const float*)d_in[2];
    const float* conv_w  = (const float*)d_in[3];
    const float* dt_bias = (const float*)d_in[4];
    const float* A_log   = (const float*)d_in[5];
    const float* Dv      = (const float*)d_in[6];
    const float* norm_w  = (const float*)d_in[7];
    const float* out_w   = (const float*)d_in[8];
    const float* out_b   = (const float*)d_in[9];
    float* out = (float*)d_out;

    float *dtraw, *states, *cum, *al;
    __half *proj, *xbc, *y, *prev, *Pm, *Af, *W1, *W2;
    cudaGetSymbolAddress((void**)&proj,   g_proj);
    cudaGetSymbolAddress((void**)&dtraw,  g_dtraw);
    cudaGetSymbolAddress((void**)&xbc,    g_xbc);
    cudaGetSymbolAddress((void**)&y,      g_y);
    cudaGetSymbolAddress((void**)&states, g_states);
    cudaGetSymbolAddress((void**)&prev,   g_prev);
    cudaGetSymbolAddress((void**)&cum,    g_cum);
    cudaGetSymbolAddress((void**)&al,     g_alast);
    cudaGetSymbolAddress((void**)&Pm,     g_P);
    cudaGetSymbolAddress((void**)&Af,     g_Af);
    cudaGetSymbolAddress((void**)&W1,     g_W1);
    cudaGetSymbolAddress((void**)&W2,     g_W2);

    const int SMEM_PMAT  = (128 * 68 * 2) * 4;
    const int SMEM_INTRA = 65536 + (256 * 4 + 8) * 4;   // 69664
    const int SMEM_OFF   = 49152 + 256 * 4;             // 50176
    cudaFuncSetAttribute(pmat_kernel,
                         cudaFuncAttributeMaxDynamicSharedMemorySize, SMEM_PMAT);
    cudaFuncSetAttribute(scan_intra_kernel,
                         cudaFuncAttributeMaxDynamicSharedMemorySize, SMEM_INTRA);
    cudaFuncSetAttribute(scan_off_kernel,
                         cudaFuncAttributeMaxDynamicSharedMemorySize, SMEM_OFF);
    cudaFuncSetAttribute(tc_gemm_bias<__half>,
                         cudaFuncAttributeMaxDynamicSharedMemorySize, GSMEM);
    cudaFuncSetAttribute(tc_gemm_bias<float>,
                         cudaFuncAttributeMaxDynamicSharedMemorySize, GSMEM);

    // 0. fp16 conversions
    {
        size_t n4 = (size_t)MT * HIDDEN_ / 4;
        cvt_fp16_kernel<<<(int)((n4 + 255) / 256), 256>>>(
            (const float4*)hidden, (__half2*)Af, n4);
        size_t n4v = (size_t)PROJ_ * HIDDEN_ / 4, n4t = (size_t)NP1 * HIDDEN_ / 4;
        cvt_fp16_pad_kernel<<<(int)((n4t + 255) / 256), 256>>>(
            (const float4*)in_w, (__half2*)W1, n4v, n4t);
        n4 = (size_t)HIDDEN_ * INTER_ / 4;
        cvt_fp16_kernel<<<(int)((n4 + 255) / 256), 256>>>(
            (const float4*)out_w, (__half2*)W2, n4);
    }

    // 1. in_proj GEMM + bias -> fp16 proj + fp32 dt side-channel
    tc_gemm_bias<__half><<<dim3(NP1 / 128, MT / 128), 256, GSMEM>>>(
        Af, W1, in_b, proj, dtraw, PROJ_, HIDDEN_);

    // 2. causal depthwise conv + SiLU -> fp16 xbc
    conv_silu_kernel<<<dim3(CONVD_ / 256, Ll / 128, Bb), 256>>>(proj, conv_w, xbc);

    // 2b. shared P = C * B^T per (b, chunk) -> fp16
    pmat_kernel<<<dim3(10, NC_, Bb), 256, SMEM_PMAT>>>(xbc, Pm);

    // 3. intra-chunk scan (double-buffered, warp-scan cumsum)
    scan_intra_kernel<<<dim3(NH_, NC_, Bb), 256, SMEM_INTRA>>>(
        dtraw, xbc, Pm, dt_bias, A_log, y, states, cum, al);

    // 4. inter-chunk recurrence -> fp16 prev
    interchunk_kernel<<<Bb * NH_, 256>>>(states, al, prev);

    // 5. inter-chunk output contribution + D skip (double-buffered)
    scan_off_kernel<<<dim3(NH_, NC_, Bb), 256, SMEM_OFF>>>(xbc, cum, prev, Dv, y);

    // 6. gated RMSNorm -> fp16 A for GEMM2
    gated_norm_kernel<<<MT, 256>>>(proj, y, norm_w, Af);

    // 7. out_proj GEMM + bias -> fp32 out
    tc_gemm_bias<float><<<dim3(HIDDEN_ / 128, MT / 128), 256, GSMEM>>>(
        Af, W2, out_b, out, nullptr, HIDDEN_, INTER_);
}